// round 11
// baseline (speedup 1.0000x reference)
#include <cuda_runtime.h>
#include <cuda_bf16.h>
#include <math.h>

#define BATCH   32768
#define EPS     1e-5f

typedef unsigned int  u32;
typedef unsigned short u16;
typedef unsigned long long u64;

// ---------------- scratch ----------------------------------------------------
__device__ float g_h [ (size_t)BATCH * 300 ];
__device__ float g_m [ (size_t)BATCH * 400 ];
__device__ float g_ap[ (size_t)BATCH * 150 ];
__device__ float g_a [ (size_t)BATCH * 63  ];

#define STATS_TOTAL 860
__device__ float g_sum  [STATS_TOTAL];
__device__ float g_sq   [STATS_TOTAL];
__device__ float g_scale[STATS_TOTAL];
__device__ float g_shift[STATS_TOTAL];

__device__ __forceinline__ float* sel_buf(int s) {
    switch (s) {
        case 0: return g_h;
        case 1: return g_m;
        case 2: return g_ap;
        case 3: return g_a;
    }
    return nullptr;
}

__global__ void zero_stats_kernel() {
    int i = blockIdx.x * blockDim.x + threadIdx.x;
    if (i < STATS_TOTAL) { g_sum[i] = 0.f; g_sq[i] = 0.f; }
}

__global__ void finalize_stats_kernel(const float* __restrict__ g,
                                      const float* __restrict__ be,
                                      int off, int n, float invB) {
    int i = blockIdx.x * blockDim.x + threadIdx.x;
    if (i < n) {
        float mean = g_sum[off + i] * invB;
        float var  = g_sq [off + i] * invB - mean * mean;
        float s    = g[i] * rsqrtf(var + EPS);
        g_scale[off + i] = s;
        g_shift[off + i] = be[i] - mean * s;
    }
}

// ---------------- bf16 helpers -----------------------------------------------
__device__ __forceinline__ void bsplit(float v, u16& h, u16& l) {
    __nv_bfloat16 hb = __float2bfloat16(v);
    h = __bfloat16_as_ushort(hb);
    float r = v - __bfloat162float(hb);
    l = __bfloat16_as_ushort(__float2bfloat16(r));
}

__device__ __forceinline__ void mma_bf16(float c[4], const u32 a[4],
                                         u32 b0, u32 b1) {
    asm("mma.sync.aligned.m16n8k16.row.col.f32.bf16.bf16.f32 "
        "{%0,%1,%2,%3}, {%4,%5,%6,%7}, {%8,%9}, {%0,%1,%2,%3};"
        : "+f"(c[0]), "+f"(c[1]), "+f"(c[2]), "+f"(c[3])
        : "r"(a[0]), "r"(a[1]), "r"(a[2]), "r"(a[3]), "r"(b0), "r"(b1));
}

// ============================================================================
// bf16-split tensor GEMM: BM=128, BN=128, BK=16, 256 threads (8 warps 2m x 4n),
// warp tile 64x32, mma.m16n8k16, 3 mma per split product.
// Smem staged in FRAGMENT ORDER: A regs -> LDS.128, B regs -> LDS.64.
// ============================================================================
template<bool RELU, bool STATS, bool NORM>
__global__ void __launch_bounds__(256)
tgemm_kernel(const float* __restrict__ Aext, int Asel,
             const float* __restrict__ W,
             const float* __restrict__ bias,
             int normOff,
             float* __restrict__ Cext, int Csel, size_t cBudget,
             int statOff,
             int N, int K)
{
    const int BM = 128, BN = 128, BK = 16;
    // A: 8 m-regions (16 rows x 16 k), per lane 4 packed-bf16x2 regs
    __shared__ __align__(16) u32 AhF[8][32][4], AlF[8][32][4];
    // B: 16 n-regions (16 k x 8 n), per lane 2 regs stored as 4 ushorts
    __shared__ __align__(8)  u16 BhF[16][32][4], BlF[16][32][4];
    __shared__ float sSum[BN], sSq[BN];

    const float* A = (Asel >= 0) ? sel_buf(Asel) : Aext;
    float*       C = (Csel >= 0) ? sel_buf(Csel) : Cext;

    const int m0   = blockIdx.y * BM;
    const int n0   = blockIdx.x * BN;
    const int tid  = threadIdx.x;
    const int wid  = tid >> 5;
    const int lane = tid & 31;
    const int g    = lane >> 2;
    const int tg   = lane & 3;
    const int wm   = (wid >> 2) * 64;      // 0 or 64
    const int wn   = (wid & 3) * 32;       // 0,32,64,96
    const int rm0  = (wid >> 2) * 4;
    const int un0  = (wid & 3) * 4;

    // A staging coords: 128 rows x 16 k, thread -> row tid/2, 8 k vals
    const int arow = tid >> 1;
    const int ak   = (tid & 1) * 8;
    const int s_rm = arow >> 4;
    const int s_ri = arow & 15;
    const int s_i  = s_ri >> 3;
    const int s_g  = s_ri & 7;
    const int s_jj = ak >> 3;
    const float* Arow = A + (size_t)(m0 + arow) * K;

    // B staging coords: 16 k x 128 n, thread -> k tid/16, 8 cols
    const int bk    = tid >> 4;
    const int bn8   = (tid & 15) * 8;
    const int bHalf = bk & 1;
    const int bPair = bk >> 1;
    const int bTg   = bPair & 3;
    const int bJJ   = bPair >> 2;

    if (tid < BN) { sSum[tid] = 0.f; sSq[tid] = 0.f; }

    float c[4][4][4];
    #pragma unroll
    for (int t = 0; t < 4; t++)
        #pragma unroll
        for (int u = 0; u < 4; u++)
            #pragma unroll
            for (int v = 0; v < 4; v++) c[t][u][v] = 0.f;

    for (int k0 = 0; k0 < K; k0 += BK) {
        // ---- stage A (split, fragment order) -------------------------------
        {
            float v[8];
            #pragma unroll
            for (int q = 0; q < 8; q++) {
                int k = k0 + ak + q;
                float x = 0.f;
                if (k < K) {
                    x = Arow[k];
                    if (NORM) x = fmaf(x, g_scale[normOff + k], g_shift[normOff + k]);
                }
                v[q] = x;
            }
            #pragma unroll
            for (int p = 0; p < 4; p++) {
                u16 h0, l0, h1, l1;
                bsplit(v[2*p],     h0, l0);
                bsplit(v[2*p + 1], h1, l1);
                int ln  = s_g * 4 + p;          // tg = p
                int reg = s_i + 2 * s_jj;
                AhF[s_rm][ln][reg] = (u32)h0 | ((u32)h1 << 16);
                AlF[s_rm][ln][reg] = (u32)l0 | ((u32)l1 << 16);
            }
        }
        // ---- stage B (split, fragment order) -------------------------------
        {
            int k = k0 + bk;
            const float* wr = W + (size_t)k * N;
            #pragma unroll
            for (int j = 0; j < 8; j++) {
                int cl = bn8 + j;
                int n  = n0 + cl;
                float x = (k < K && n < N) ? wr[n] : 0.f;
                u16 h, l;
                bsplit(x, h, l);
                int un = cl >> 3;
                int ln = (cl & 7) * 4 + bTg;
                BhF[un][ln][bJJ * 2 + bHalf] = h;
                BlF[un][ln][bJJ * 2 + bHalf] = l;
            }
        }
        __syncthreads();

        // ---- compute: 8 LDS.128 (A) + 8 LDS.64 (B) + 48 mma ----------------
        u32 ah[4][4], al[4][4];
        #pragma unroll
        for (int t = 0; t < 4; t++) {
            *(uint4*)ah[t] = *(const uint4*)&AhF[rm0 + t][lane][0];
            *(uint4*)al[t] = *(const uint4*)&AlF[rm0 + t][lane][0];
        }
        #pragma unroll
        for (int u = 0; u < 4; u++) {
            uint2 bh = *(const uint2*)&BhF[un0 + u][lane][0];
            uint2 bl = *(const uint2*)&BlF[un0 + u][lane][0];
            #pragma unroll
            for (int t = 0; t < 4; t++) {
                mma_bf16(c[t][u], ah[t], bh.x, bh.y);   // hi*hi
                mma_bf16(c[t][u], al[t], bh.x, bh.y);   // lo*hi
                mma_bf16(c[t][u], ah[t], bl.x, bl.y);   // hi*lo
            }
        }
        __syncthreads();
    }

    // ---- epilogue: bias, relu, store, stats ---------------------------------
    float colS[8], colQ[8];
    #pragma unroll
    for (int j = 0; j < 8; j++) { colS[j] = 0.f; colQ[j] = 0.f; }

    #pragma unroll
    for (int t = 0; t < 4; t++) {
        const int r0 = m0 + wm + t * 16 + g;
        #pragma unroll
        for (int u = 0; u < 4; u++) {
            const int colb = n0 + wn + u * 8 + 2 * tg;
            const float bv0 = (colb < N)     ? bias[colb]     : 0.f;
            const float bv1 = (colb + 1 < N) ? bias[colb + 1] : 0.f;
            float x0 = c[t][u][0] + bv0, x1 = c[t][u][1] + bv1;
            float x2 = c[t][u][2] + bv0, x3 = c[t][u][3] + bv1;
            if (RELU) {
                x0 = fmaxf(x0, 0.f); x1 = fmaxf(x1, 0.f);
                x2 = fmaxf(x2, 0.f); x3 = fmaxf(x3, 0.f);
            }
            const size_t i0 = (size_t)r0 * N + colb;
            const size_t i1 = (size_t)(r0 + 8) * N + colb;
            if (colb + 1 < N) {
                if ((i0 + 2) * 4 <= cBudget) *(float2*)(C + i0) = make_float2(x0, x1);
                if ((i1 + 2) * 4 <= cBudget) *(float2*)(C + i1) = make_float2(x2, x3);
            } else if (colb < N) {
                if ((i0 + 1) * 4 <= cBudget) C[i0] = x0;
                if ((i1 + 1) * 4 <= cBudget) C[i1] = x2;
            }
            if (STATS) {
                const int j = u * 2;
                if (colb < N)     { colS[j]   += x0 + x2; colQ[j]   += x0*x0 + x2*x2; }
                if (colb + 1 < N) { colS[j+1] += x1 + x3; colQ[j+1] += x1*x1 + x3*x3; }
            }
        }
    }

    if (STATS) {
        #pragma unroll
        for (int u = 0; u < 4; u++)
            #pragma unroll
            for (int p = 0; p < 2; p++) {
                int ln = wn + u * 8 + 2 * tg + p;
                atomicAdd(&sSum[ln], colS[u * 2 + p]);
                atomicAdd(&sSq [ln], colQ[u * 2 + p]);
            }
        __syncthreads();
        if (tid < BN) {
            int n = n0 + tid;
            if (n < N) {
                atomicAdd(&g_sum[statOff + n], sSum[tid]);
                atomicAdd(&g_sq [statOff + n], sSq [tid]);
            }
        }
    }
}

// ---------------- FFMA2 GEMM (layer 1, K=24) --------------------------------
__device__ __forceinline__ u64 pack_dup(float x) {
    u64 r;
    asm("mov.b64 %0, {%1, %1};" : "=l"(r) : "r"(__float_as_uint(x)));
    return r;
}
__device__ __forceinline__ void unpack2(u64 v, float& x, float& y) {
    u32 a, b;
    asm("mov.b64 {%0, %1}, %2;" : "=r"(a), "=r"(b) : "l"(v));
    x = __uint_as_float(a);
    y = __uint_as_float(b);
}
__device__ __forceinline__ void fma2(u64& d, u64 a, u64 b) {
    asm("fma.rn.f32x2 %0, %1, %2, %3;" : "=l"(d) : "l"(a), "l"(b), "l"(d));
}

template<bool NORM>
__device__ __forceinline__ void load_A_regs(const float* __restrict__ Arow,
                                            int k0, int K, int normOff,
                                            float av[16])
{
    if (k0 + 16 <= K) {
        const float4* p = (const float4*)(Arow + k0);
        float4 t0 = p[0], t1 = p[1], t2 = p[2], t3 = p[3];
        av[0]=t0.x; av[1]=t0.y; av[2]=t0.z; av[3]=t0.w;
        av[4]=t1.x; av[5]=t1.y; av[6]=t1.z; av[7]=t1.w;
        av[8]=t2.x; av[9]=t2.y; av[10]=t2.z; av[11]=t2.w;
        av[12]=t3.x; av[13]=t3.y; av[14]=t3.z; av[15]=t3.w;
        if (NORM) {
            #pragma unroll
            for (int q = 0; q < 16; q++)
                av[q] = fmaf(av[q], g_scale[normOff + k0 + q],
                                    g_shift[normOff + k0 + q]);
        }
    } else {
        #pragma unroll
        for (int q = 0; q < 16; q++) {
            int k = k0 + q;
            float v = 0.f;
            if (k < K) {
                v = Arow[k];
                if (NORM) v = fmaf(v, g_scale[normOff + k], g_shift[normOff + k]);
            }
            av[q] = v;
        }
    }
}

__device__ __forceinline__ void load_W_regs(const float* __restrict__ W,
                                            int k0, int wk, int n0, int wn,
                                            int N, int K, bool wVec,
                                            float4& w0, float4& w1)
{
    w0 = make_float4(0.f,0.f,0.f,0.f);
    w1 = w0;
    int k = k0 + wk;
    int n = n0 + wn;
    if (k < K) {
        const float* wr = W + (size_t)k * N;
        if (wVec && n + 8 <= N) {
            w0 = *(const float4*)(wr + n);
            w1 = *(const float4*)(wr + n + 4);
        } else {
            float t[8];
            #pragma unroll
            for (int j = 0; j < 8; j++)
                t[j] = (n + j < N) ? wr[n + j] : 0.f;
            w0 = make_float4(t[0],t[1],t[2],t[3]);
            w1 = make_float4(t[4],t[5],t[6],t[7]);
        }
    }
}

template<bool RELU, bool STATS, bool NORM>
__global__ void __launch_bounds__(128)
fgemm_kernel(const float* __restrict__ Aext, int Asel,
             const float* __restrict__ W,
             const float* __restrict__ bias,
             int normOff,
             float* __restrict__ Cext, int Csel, size_t cBudget,
             int statOff,
             int N, int K)
{
    const int BN = 64, BK = 16;
    __shared__ __align__(16) float As[2][BK][128];
    __shared__ __align__(16) float Ws[2][BK][BN];
    __shared__ float sSum[BN], sSq[BN];

    const float* A = (Asel >= 0) ? sel_buf(Asel) : Aext;
    float*       C = (Csel >= 0) ? sel_buf(Csel) : Cext;

    const int m0  = blockIdx.y * 128;
    const int n0  = blockIdx.x * BN;
    const int tid = threadIdx.x;
    const int mg  = tid >> 3;
    const int ng  = tid & 7;
    const int wk  = tid >> 3;
    const int wn  = (tid & 7) * 8;

    const float* Arow = A + (size_t)(m0 + tid) * K;
    const bool wVec = ((N & 3) == 0);

    u64 acc2[8][4];
    #pragma unroll
    for (int i = 0; i < 8; i++)
        #pragma unroll
        for (int p = 0; p < 4; p++) acc2[i][p] = 0ull;

    const int nTiles = (K + BK - 1) / BK;

    float av[16];
    float4 w0, w1;
    load_A_regs<NORM>(Arow, 0, K, normOff, av);
    load_W_regs(W, 0, wk, n0, wn, N, K, wVec, w0, w1);
    #pragma unroll
    for (int q = 0; q < 16; q++) As[0][q][tid] = av[q];
    *(float4*)&Ws[0][wk][wn]     = w0;
    *(float4*)&Ws[0][wk][wn + 4] = w1;
    __syncthreads();

    for (int t = 0; t < nTiles; t++) {
        const int buf = t & 1;
        const bool more = (t + 1 < nTiles);
        if (more) {
            load_A_regs<NORM>(Arow, (t + 1) * BK, K, normOff, av);
            load_W_regs(W, (t + 1) * BK, wk, n0, wn, N, K, wVec, w0, w1);
        }
        #pragma unroll
        for (int kk = 0; kk < BK; kk++) {
            float4 a0 = *(const float4*)&As[buf][kk][mg * 8];
            float4 a1 = *(const float4*)&As[buf][kk][mg * 8 + 4];
            ulonglong2 bq0 = *(const ulonglong2*)&Ws[buf][kk][ng * 4];
            ulonglong2 bq1 = *(const ulonglong2*)&Ws[buf][kk][32 + ng * 4];
            u64 bb[4] = { bq0.x, bq0.y, bq1.x, bq1.y };
            float ar[8] = {a0.x,a0.y,a0.z,a0.w,a1.x,a1.y,a1.z,a1.w};
            #pragma unroll
            for (int i = 0; i < 8; i++) {
                u64 ai = pack_dup(ar[i]);
                #pragma unroll
                for (int p = 0; p < 4; p++)
                    fma2(acc2[i][p], ai, bb[p]);
            }
        }
        if (more) {
            const int nb = buf ^ 1;
            #pragma unroll
            for (int q = 0; q < 16; q++) As[nb][q][tid] = av[q];
            *(float4*)&Ws[nb][wk][wn]     = w0;
            *(float4*)&Ws[nb][wk][wn + 4] = w1;
            __syncthreads();
        }
    }

    float colSum[8], colSq[8];
    #pragma unroll
    for (int j = 0; j < 8; j++) { colSum[j] = 0.f; colSq[j] = 0.f; }

    const int cA = n0 + ng * 4;
    const int cB = n0 + 32 + ng * 4;
    float bvA[4], bvB[4];
    #pragma unroll
    for (int j = 0; j < 4; j++) {
        bvA[j] = (cA + j < N) ? bias[cA + j] : 0.f;
        bvB[j] = (cB + j < N) ? bias[cB + j] : 0.f;
    }

    #pragma unroll
    for (int i = 0; i < 8; i++) {
        const int m = m0 + mg * 8 + i;
        float vA[4], vB[4];
        unpack2(acc2[i][0], vA[0], vA[1]);
        unpack2(acc2[i][1], vA[2], vA[3]);
        unpack2(acc2[i][2], vB[0], vB[1]);
        unpack2(acc2[i][3], vB[2], vB[3]);
        #pragma unroll
        for (int j = 0; j < 4; j++) {
            float cc = vA[j] + bvA[j];
            if (RELU) cc = fmaxf(cc, 0.f);
            vA[j] = cc;
            if (STATS && cA + j < N) { colSum[j] += cc; colSq[j] += cc * cc; }
            cc = vB[j] + bvB[j];
            if (RELU) cc = fmaxf(cc, 0.f);
            vB[j] = cc;
            if (STATS && cB + j < N) { colSum[4 + j] += cc; colSq[4 + j] += cc * cc; }
        }
        const size_t rowBase = (size_t)m * N;
        if (wVec && cA + 4 <= N && (rowBase + cA + 4) * 4 <= cBudget) {
            *(float4*)(C + rowBase + cA) = make_float4(vA[0],vA[1],vA[2],vA[3]);
        } else {
            #pragma unroll
            for (int j = 0; j < 4; j++)
                if (cA + j < N && (rowBase + cA + j + 1) * 4 <= cBudget)
                    C[rowBase + cA + j] = vA[j];
        }
        if (wVec && cB + 4 <= N && (rowBase + cB + 4) * 4 <= cBudget) {
            *(float4*)(C + rowBase + cB) = make_float4(vB[0],vB[1],vB[2],vB[3]);
        } else {
            #pragma unroll
            for (int j = 0; j < 4; j++)
                if (cB + j < N && (rowBase + cB + j + 1) * 4 <= cBudget)
                    C[rowBase + cB + j] = vB[j];
        }
    }

    if (STATS) {
        if (tid < BN) { sSum[tid] = 0.f; sSq[tid] = 0.f; }
        __syncthreads();
        #pragma unroll
        for (int j = 0; j < 4; j++) {
            atomicAdd(&sSum[ng * 4 + j],      colSum[j]);
            atomicAdd(&sSq [ng * 4 + j],      colSq [j]);
            atomicAdd(&sSum[32 + ng * 4 + j], colSum[4 + j]);
            atomicAdd(&sSq [32 + ng * 4 + j], colSq [4 + j]);
        }
        __syncthreads();
        if (tid < BN) {
            int n = n0 + tid;
            if (n < N) {
                atomicAdd(&g_sum[statOff + n], sSum[tid]);
                atomicAdd(&g_sq [statOff + n], sSq [tid]);
            }
        }
    }
}

// ---------------- small scalar GEMM (N=63 final projection) ----------------
template<bool RELU, bool STATS, bool NORM>
__global__ void __launch_bounds__(256, 4)
sgemm_kernel(const float* __restrict__ Aext, int Asel,
             const float* __restrict__ W,
             const float* __restrict__ bias,
             int normOff,
             float* __restrict__ Cext, int Csel,
             int statOff,
             int N, int K)
{
    const int BN = 64, BK = 8, TM = 8, TN = 4;
    __shared__ float As[BK][128];
    __shared__ float Ws[BK][BN];

    const float* A = (Asel >= 0) ? sel_buf(Asel) : Aext;
    float*       C = (Csel >= 0) ? sel_buf(Csel) : Cext;

    const int m0  = blockIdx.y * 128;
    const int n0  = blockIdx.x * BN;
    const int tid = threadIdx.x;
    const int tx  = tid & 15;
    const int ty  = tid >> 4;

    float acc[TM][TN];
    #pragma unroll
    for (int i = 0; i < TM; i++)
        #pragma unroll
        for (int j = 0; j < TN; j++) acc[i][j] = 0.f;

    for (int k0 = 0; k0 < K; k0 += BK) {
        #pragma unroll
        for (int i = 0; i < 4; i++) {
            int idx = tid + i * 256;
            int mm  = idx >> 3;
            int kk  = idx & 7;
            int k   = k0 + kk;
            float v = 0.f;
            if (k < K) {
                v = A[(size_t)(m0 + mm) * K + k];
                if (NORM) v = fmaf(v, g_scale[normOff + k], g_shift[normOff + k]);
            }
            As[kk][mm] = v;
        }
        #pragma unroll
        for (int i = 0; i < 2; i++) {
            int idx = tid + i * 256;
            int kk  = idx >> 6;
            int nn  = idx & 63;
            int k   = k0 + kk, n = n0 + nn;
            Ws[kk][nn] = (k < K && n < N) ? W[(size_t)k * N + n] : 0.f;
        }
        __syncthreads();
        #pragma unroll
        for (int kk = 0; kk < BK; kk++) {
            float ar[TM], br[TN];
            #pragma unroll
            for (int i = 0; i < TM; i++) ar[i] = As[kk][ty * TM + i];
            #pragma unroll
            for (int j = 0; j < TN; j++) br[j] = Ws[kk][tx * TN + j];
            #pragma unroll
            for (int i = 0; i < TM; i++)
                #pragma unroll
                for (int j = 0; j < TN; j++)
                    acc[i][j] = fmaf(ar[i], br[j], acc[i][j]);
        }
        __syncthreads();
    }

    #pragma unroll
    for (int j = 0; j < TN; j++) {
        int n = n0 + tx * TN + j;
        if (n < N) {
            float bv = bias[n];
            #pragma unroll
            for (int i = 0; i < TM; i++) {
                float c = acc[i][j] + bv;
                if (RELU) c = fmaxf(c, 0.f);
                C[(size_t)(m0 + ty * TM + i) * N + n] = c;
            }
        }
    }
}

// ---------------- Toeplitz epilogue (REAL parts only) -----------------------
__global__ void __launch_bounds__(256)
toeplitz_real_kernel(float* __restrict__ out,
                     size_t offB, size_t offC, size_t budgetElems)
{
    __shared__ float sre[8][32];
    const int warp = threadIdx.x >> 5;
    const int lane = threadIdx.x & 31;
    const int row  = blockIdx.x * 8 + warp;

    const float* ar = g_a + (size_t)row * 63;
    float v0 = ar[lane];
    float a0 = fminf(expf(__shfl_sync(0xffffffffu, v0, 0)), 500.f);

    float re = (lane == 0) ? a0 : (0.022f * a0 * tanhf(v0));
    sre[warp][lane] = re;
    __syncwarp();

    const size_t rbase = (size_t)row * 1024 + lane;
    #pragma unroll
    for (int i = 0; i < 32; i++) {
        int d = i - lane;
        float b = (d >= 0) ? sre[warp][d]      : 0.f;
        float c = (d >= 1) ? sre[warp][32 - d] : 0.f;
        size_t ib = offB + rbase + (size_t)i * 32;
        size_t ic = offC + rbase + (size_t)i * 32;
        if (ib < budgetElems) out[ib] = b;
        if (ic < budgetElems) out[ic] = c;
    }
}

// ---------------- launch -----------------------------------------------------
extern "C" void kernel_launch(void* const* d_in, const int* in_sizes, int n_in,
                              void* d_out, int out_size)
{
    if (n_in < 17) return;

    const float* z   = (const float*)d_in[0];
    const float* W1  = (const float*)d_in[1];
    const float* b1  = (const float*)d_in[2];
    const float* g1  = (const float*)d_in[3];
    const float* be1 = (const float*)d_in[4];
    const float* W2  = (const float*)d_in[5];
    const float* b2  = (const float*)d_in[6];
    const float* g2  = (const float*)d_in[7];
    const float* be2 = (const float*)d_in[8];
    const float* W3  = (const float*)d_in[9];
    const float* b3  = (const float*)d_in[10];
    const float* Wa1 = (const float*)d_in[11];
    const float* ba1 = (const float*)d_in[12];
    const float* ga  = (const float*)d_in[13];
    const float* bea = (const float*)d_in[14];
    const float* Wa2 = (const float*)d_in[15];
    const float* ba2 = (const float*)d_in[16];

    long long Braw = (long long)in_sizes[0] / 24;
    if (Braw > BATCH) Braw = BATCH;
    Braw -= (Braw % 128);
    if (Braw <= 0) return;
    const int B = (int)Braw;
    const long long LB = (long long)B;

    float* out = (float*)d_out;
    const float invB = 1.0f / (float)B;
    const size_t budgetBytes = (size_t)out_size * 4;
    const size_t budgetElems = (size_t)out_size;
    const size_t BIG = (size_t)-1;
    const int mB = B / 128;

    zero_stats_kernel<<<4, 256>>>();

    // 1. h = relu(z @ W1 + b1)            (K=24, N=300) [FFMA2]
    fgemm_kernel<true, true, false><<<dim3(5, mB), 128>>>(
        z, -1, W1, b1, 0, nullptr, 0, BIG, 0, 300, 24);

    finalize_stats_kernel<<<2, 256>>>(g1, be1, 0, 300, invB);

    // 3. m = relu(BN(h) @ W2 + b2)        (K=300, N=400) [bf16 tensor]
    tgemm_kernel<true, true, true><<<dim3(4, mB), 256>>>(
        nullptr, 0, W2, b2, 0, nullptr, 1, BIG, 300, 400, 300);

    // 4. ap = relu(BN(h) @ Wa1 + ba1)     (K=300, N=150) [bf16 tensor]
    tgemm_kernel<true, true, true><<<dim3(2, mB), 256>>>(
        nullptr, 0, Wa1, ba1, 0, nullptr, 2, BIG, 700, 150, 300);

    finalize_stats_kernel<<<2, 256>>>(g2, be2, 300, 400, invB);
    finalize_stats_kernel<<<1, 256>>>(ga, bea, 700, 150, invB);

    // 6. mu_out = BN(m) @ W3 + b3         (K=400, N=1024) [bf16 tensor]
    tgemm_kernel<false, false, true><<<dim3(8, mB), 256>>>(
        nullptr, 1, W3, b3, 300, out, -1, budgetBytes, 0, 1024, 400);

    // 7. a = BN(ap) @ Wa2 + ba2           (K=150, N=63) [scalar]
    sgemm_kernel<false, false, true><<<dim3(1, mB), 256>>>(
        nullptr, 2, Wa2, ba2, 700, nullptr, 3, 0, 63, 150);

    // 8. Toeplitz real parts
    toeplitz_real_kernel<<<B / 8, 256>>>(out, (size_t)LB * 1024,
                                         (size_t)LB * 2048, budgetElems);
}

// round 12
// speedup vs baseline: 1.5875x; 1.5875x over previous
#include <cuda_runtime.h>
#include <cuda_bf16.h>
#include <math.h>

#define BATCH 32768
#define EPS   1e-5f
#define KP_H  320     // padded K for h planes (K=300)
#define KP_M  416     // padded K for m planes (K=400)

typedef unsigned int  u32;
typedef unsigned short u16;
typedef unsigned long long u64;

// ---------------- scratch (device globals) -----------------------------------
__device__ __nv_bfloat16 g_hh[(size_t)BATCH * KP_H], g_hl[(size_t)BATCH * KP_H];
__device__ __nv_bfloat16 g_mh[(size_t)BATCH * KP_M], g_ml[(size_t)BATCH * KP_M];
__device__ float g_ap[(size_t)BATCH * 150];
__device__ float g_a [(size_t)BATCH * 63];

__device__ __nv_bfloat16 g_W2h [400  * KP_H], g_W2l [400  * KP_H];
__device__ __nv_bfloat16 g_Wa1h[150  * KP_H], g_Wa1l[150  * KP_H];
__device__ __nv_bfloat16 g_W3h [1024 * KP_M], g_W3l [1024 * KP_M];
__device__ float g_bp2[400], g_bpa[150], g_bp3[1024];

#define STATS_TOTAL 860
__device__ float g_sum  [STATS_TOTAL];
__device__ float g_sq   [STATS_TOTAL];
__device__ float g_scale[STATS_TOTAL];
__device__ float g_shift[STATS_TOTAL];

__device__ __forceinline__ __nv_bfloat16* sel_bf(int s) {
    switch (s) {
        case 0: return g_hh;   case 1: return g_hl;
        case 2: return g_mh;   case 3: return g_ml;
        case 4: return g_W2h;  case 5: return g_W2l;
        case 6: return g_Wa1h; case 7: return g_Wa1l;
        case 8: return g_W3h;  case 9: return g_W3l;
    }
    return nullptr;
}
__device__ __forceinline__ float* sel_f(int s) {
    switch (s) {
        case 2: return g_bp2;  case 3: return g_bpa;  case 4: return g_bp3;
    }
    return nullptr;
}

__global__ void zero_stats_kernel() {
    int i = blockIdx.x * blockDim.x + threadIdx.x;
    if (i < STATS_TOTAL) { g_sum[i] = 0.f; g_sq[i] = 0.f; }
}

// zero the k-padding columns of the activation planes
__global__ void padzero_kernel(int B) {
    int idx = blockIdx.x * blockDim.x + threadIdx.x;
    const __nv_bfloat16 z = __float2bfloat16(0.f);
    if (idx < B * 20) {
        int r = idx / 20, c = idx % 20;
        g_hh[(size_t)r * KP_H + 300 + c] = z;
        g_hl[(size_t)r * KP_H + 300 + c] = z;
    } else {
        idx -= B * 20;
        if (idx < B * 16) {
            int r = idx / 16, c = idx % 16;
            g_mh[(size_t)r * KP_M + 400 + c] = z;
            g_ml[(size_t)r * KP_M + 400 + c] = z;
        }
    }
}

__global__ void finalize_stats_kernel(const float* __restrict__ g,
                                      const float* __restrict__ be,
                                      int off, int n, float invB) {
    int i = blockIdx.x * blockDim.x + threadIdx.x;
    if (i < n) {
        float mean = g_sum[off + i] * invB;
        float var  = g_sq [off + i] * invB - mean * mean;
        float s    = g[i] * rsqrtf(var + EPS);
        g_scale[off + i] = s;
        g_shift[off + i] = be[i] - mean * s;
    }
}

// ---------------- bf16 split helper ------------------------------------------
__device__ __forceinline__ void bsplit(float v, __nv_bfloat16& h, __nv_bfloat16& l) {
    h = __float2bfloat16(v);
    l = __float2bfloat16(v - __bfloat162float(h));
}

// ---------------- weight fold: Wh/Wl[N][Kp] = split(scale[k]*W[k][n]) --------
// bp[n] = bias[n] + sum_k shift[k]*W[k][n]
__global__ void __launch_bounds__(128)
fold_kernel(const float* __restrict__ W, const float* __restrict__ bias,
            int scOff, int N, int K, int Kp, int wSel, int bpSel)
{
    __shared__ float red[128];
    const int n = blockIdx.x;
    const int tid = threadIdx.x;
    __nv_bfloat16* Wh = sel_bf(wSel);
    __nv_bfloat16* Wl = sel_bf(wSel + 1);
    float* bp = sel_f(bpSel);

    float acc = 0.f;
    for (int k = tid; k < Kp; k += 128) {
        float w = 0.f, sc = 0.f, sh = 0.f;
        if (k < K) {
            w  = W[(size_t)k * N + n];
            sc = g_scale[scOff + k];
            sh = g_shift[scOff + k];
        }
        float wp = w * sc;
        __nv_bfloat16 h, l;
        bsplit(wp, h, l);
        Wh[(size_t)n * Kp + k] = h;
        Wl[(size_t)n * Kp + k] = l;
        acc += sh * w;
    }
    red[tid] = acc;
    __syncthreads();
    #pragma unroll
    for (int s = 64; s > 0; s >>= 1) {
        if (tid < s) red[tid] += red[tid + s];
        __syncthreads();
    }
    if (tid == 0) bp[n] = bias[n] + red[0];
}

// ---------------- mma / ldmatrix wrappers -------------------------------------
__device__ __forceinline__ void mma_bf16(float c[4], const u32 a[4],
                                         u32 b0, u32 b1) {
    asm volatile("mma.sync.aligned.m16n8k16.row.col.f32.bf16.bf16.f32 "
        "{%0,%1,%2,%3}, {%4,%5,%6,%7}, {%8,%9}, {%0,%1,%2,%3};"
        : "+f"(c[0]), "+f"(c[1]), "+f"(c[2]), "+f"(c[3])
        : "r"(a[0]), "r"(a[1]), "r"(a[2]), "r"(a[3]), "r"(b0), "r"(b1));
}
__device__ __forceinline__ void ldsm_x4(u32& r0, u32& r1, u32& r2, u32& r3, u32 addr) {
    asm volatile("ldmatrix.sync.aligned.m8n8.x4.shared.b16 {%0,%1,%2,%3}, [%4];"
        : "=r"(r0), "=r"(r1), "=r"(r2), "=r"(r3) : "r"(addr));
}

// ============================================================================
// bf16-split tensor GEMM. BM=128, BN=128, BK=32, 256 thr (8 warps, 2m x 4n),
// warp tile 64x32. A/B pre-split bf16 planes, zero-padded K. ldmatrix frags
// from 80B-strided smem rows (conflict-free).
// OUTMODE: 0 = f32 to Cext (budget-guarded), 1 = f32 to g_ap, 2 = split to g_m*
// ============================================================================
template<bool RELU, bool STATS, int OUTMODE>
__global__ void __launch_bounds__(256)
bgemm_kernel(int aSel, int aKP, int bSel, int bpSel,
             float* __restrict__ Cext, size_t cBudget,
             int statOff, int N, int K)
{
    __shared__ __align__(16) __nv_bfloat16 sAh[128 * 40], sAl[128 * 40];
    __shared__ __align__(16) __nv_bfloat16 sBh[128 * 40], sBl[128 * 40];
    __shared__ float sSum[128], sSq[128];

    const __nv_bfloat16* Ah = sel_bf(aSel);
    const __nv_bfloat16* Al = sel_bf(aSel + 1);
    const __nv_bfloat16* Bh = sel_bf(bSel);
    const __nv_bfloat16* Bl = sel_bf(bSel + 1);
    const float* bp = sel_f(bpSel);

    const int m0 = blockIdx.y * 128, n0 = blockIdx.x * 128;
    const int tid = threadIdx.x, wid = tid >> 5, lane = tid & 31;
    const int g = lane >> 2, tg = lane & 3;
    const int wm = (wid >> 2) * 64, wn = (wid & 3) * 32;

    if (tid < 128) { sSum[tid] = 0.f; sSq[tid] = 0.f; }

    // staging coords: thread -> (row, k-half)
    const int srow = tid >> 1, shalf = tid & 1;
    const size_t aOff = (size_t)(m0 + srow) * aKP + shalf * 16;
    const int bRow = n0 + srow;
    const size_t bOff = (size_t)bRow * aKP + shalf * 16;
    const int sOff = srow * 40 + shalf * 16;

    // ldmatrix lane base offsets (bytes)
    const u32 baseAh = (u32)__cvta_generic_to_shared(sAh);
    const u32 baseAl = (u32)__cvta_generic_to_shared(sAl);
    const u32 baseBh = (u32)__cvta_generic_to_shared(sBh);
    const u32 baseBl = (u32)__cvta_generic_to_shared(sBl);
    const u32 aLOff = (u32)((wm + (lane & 15)) * 80 + (lane >> 4) * 16);
    const u32 bLOff = (u32)((wn + ((lane >> 4) & 1) * 8 + (lane & 7)) * 80
                            + ((lane >> 3) & 1) * 16);

    float c[4][4][4];
    #pragma unroll
    for (int t = 0; t < 4; t++)
        #pragma unroll
        for (int u = 0; u < 4; u++)
            #pragma unroll
            for (int v = 0; v < 4; v++) c[t][u][v] = 0.f;

    const int nT = (K + 31) / 32;
    for (int t0 = 0; t0 < nT; t0++) {
        const int k0 = t0 * 32;
        // ---- stage A (pure copies; K zero-padded) --------------------------
        {
            const uint4* p = (const uint4*)(Ah + aOff + k0);
            uint4 v0 = p[0], v1 = p[1];
            const uint4* q = (const uint4*)(Al + aOff + k0);
            uint4 w0 = q[0], w1 = q[1];
            *(uint4*)&sAh[sOff] = v0; *(uint4*)&sAh[sOff + 8] = v1;
            *(uint4*)&sAl[sOff] = w0; *(uint4*)&sAl[sOff + 8] = w1;
        }
        // ---- stage B (guard n < N) -----------------------------------------
        {
            uint4 z = make_uint4(0, 0, 0, 0);
            uint4 v0 = z, v1 = z, w0 = z, w1 = z;
            if (bRow < N) {
                const uint4* p = (const uint4*)(Bh + bOff + k0);
                v0 = p[0]; v1 = p[1];
                const uint4* q = (const uint4*)(Bl + bOff + k0);
                w0 = q[0]; w1 = q[1];
            }
            *(uint4*)&sBh[sOff] = v0; *(uint4*)&sBh[sOff + 8] = v1;
            *(uint4*)&sBl[sOff] = w0; *(uint4*)&sBl[sOff + 8] = w1;
        }
        __syncthreads();

        #pragma unroll
        for (int ks = 0; ks < 32; ks += 16) {
            u32 ah[4][4], al[4][4], bh[4][2], bl[4][2];
            #pragma unroll
            for (int t = 0; t < 4; t++) {
                u32 off = (u32)(t * 16 * 80 + ks * 2) + aLOff;
                ldsm_x4(ah[t][0], ah[t][1], ah[t][2], ah[t][3], baseAh + off);
                ldsm_x4(al[t][0], al[t][1], al[t][2], al[t][3], baseAl + off);
            }
            #pragma unroll
            for (int up = 0; up < 2; up++) {
                u32 off = (u32)(up * 16 * 80 + ks * 2) + bLOff;
                ldsm_x4(bh[2*up][0], bh[2*up][1], bh[2*up+1][0], bh[2*up+1][1],
                        baseBh + off);
                ldsm_x4(bl[2*up][0], bl[2*up][1], bl[2*up+1][0], bl[2*up+1][1],
                        baseBl + off);
            }
            // 3 passes of 16 mma; accumulator reuse distance 16
            #pragma unroll
            for (int t = 0; t < 4; t++)
                #pragma unroll
                for (int u = 0; u < 4; u++)
                    mma_bf16(c[t][u], ah[t], bh[u][0], bh[u][1]);
            #pragma unroll
            for (int t = 0; t < 4; t++)
                #pragma unroll
                for (int u = 0; u < 4; u++)
                    mma_bf16(c[t][u], al[t], bh[u][0], bh[u][1]);
            #pragma unroll
            for (int t = 0; t < 4; t++)
                #pragma unroll
                for (int u = 0; u < 4; u++)
                    mma_bf16(c[t][u], ah[t], bl[u][0], bl[u][1]);
        }
        __syncthreads();
    }

    // ---- epilogue -----------------------------------------------------------
    float colS[8], colQ[8];
    #pragma unroll
    for (int j = 0; j < 8; j++) { colS[j] = 0.f; colQ[j] = 0.f; }

    #pragma unroll
    for (int t = 0; t < 4; t++) {
        const int r0 = m0 + wm + t * 16 + g;
        const int r1 = r0 + 8;
        #pragma unroll
        for (int u = 0; u < 4; u++) {
            const int colb = n0 + wn + u * 8 + 2 * tg;
            if (colb >= N) continue;
            const float bv0 = bp[colb];
            const float bv1 = (colb + 1 < N) ? bp[colb + 1] : 0.f;
            float x0 = c[t][u][0] + bv0, x1 = c[t][u][1] + bv1;
            float x2 = c[t][u][2] + bv0, x3 = c[t][u][3] + bv1;
            if (RELU) {
                x0 = fmaxf(x0, 0.f); x1 = fmaxf(x1, 0.f);
                x2 = fmaxf(x2, 0.f); x3 = fmaxf(x3, 0.f);
            }
            if (OUTMODE == 0) {
                const size_t i0 = (size_t)r0 * N + colb;
                const size_t i1 = (size_t)r1 * N + colb;
                if (colb + 1 < N) {
                    if ((i0 + 2) * 4 <= cBudget) *(float2*)(Cext + i0) = make_float2(x0, x1);
                    if ((i1 + 2) * 4 <= cBudget) *(float2*)(Cext + i1) = make_float2(x2, x3);
                } else {
                    if ((i0 + 1) * 4 <= cBudget) Cext[i0] = x0;
                    if ((i1 + 1) * 4 <= cBudget) Cext[i1] = x2;
                }
            } else if (OUTMODE == 1) {
                if (colb + 1 < N) {
                    *(float2*)(g_ap + (size_t)r0 * N + colb) = make_float2(x0, x1);
                    *(float2*)(g_ap + (size_t)r1 * N + colb) = make_float2(x2, x3);
                } else {
                    g_ap[(size_t)r0 * N + colb] = x0;
                    g_ap[(size_t)r1 * N + colb] = x2;
                }
            } else {
                __nv_bfloat16 h0, l0, h1, l1;
                bsplit(x0, h0, l0); bsplit(x1, h1, l1);
                *(u32*)&g_mh[(size_t)r0 * KP_M + colb] =
                    (u32)__bfloat16_as_ushort(h0) | ((u32)__bfloat16_as_ushort(h1) << 16);
                *(u32*)&g_ml[(size_t)r0 * KP_M + colb] =
                    (u32)__bfloat16_as_ushort(l0) | ((u32)__bfloat16_as_ushort(l1) << 16);
                bsplit(x2, h0, l0); bsplit(x3, h1, l1);
                *(u32*)&g_mh[(size_t)r1 * KP_M + colb] =
                    (u32)__bfloat16_as_ushort(h0) | ((u32)__bfloat16_as_ushort(h1) << 16);
                *(u32*)&g_ml[(size_t)r1 * KP_M + colb] =
                    (u32)__bfloat16_as_ushort(l0) | ((u32)__bfloat16_as_ushort(l1) << 16);
            }
            if (STATS) {
                const int j = u * 2;
                colS[j] += x0 + x2; colQ[j] += x0 * x0 + x2 * x2;
                if (colb + 1 < N) { colS[j+1] += x1 + x3; colQ[j+1] += x1*x1 + x3*x3; }
            }
        }
    }

    if (STATS) {
        #pragma unroll
        for (int u = 0; u < 4; u++)
            #pragma unroll
            for (int p = 0; p < 2; p++) {
                int ln = wn + u * 8 + 2 * tg + p;
                atomicAdd(&sSum[ln], colS[u * 2 + p]);
                atomicAdd(&sSq [ln], colQ[u * 2 + p]);
            }
        __syncthreads();
        if (tid < 128) {
            int n = n0 + tid;
            if (n < N) {
                atomicAdd(&g_sum[statOff + n], sSum[tid]);
                atomicAdd(&g_sq [statOff + n], sSq [tid]);
            }
        }
    }
}

// ============================================================================
// Layer-1 GEMM (K=24, N=300): fp32 compute, writes h as bf16 split planes.
// BM=128, BN=64, BK=16, 128 threads, 8x8/thread.
// ============================================================================
__global__ void __launch_bounds__(128)
fgemm1_kernel(const float* __restrict__ A, const float* __restrict__ W,
              const float* __restrict__ bias, int N, int K)
{
    const int BN = 64, BK = 16;
    __shared__ __align__(16) float As[BK][128];
    __shared__ __align__(16) float Ws[BK][BN];
    __shared__ float sSum[BN], sSq[BN];

    const int m0  = blockIdx.y * 128;
    const int n0  = blockIdx.x * BN;
    const int tid = threadIdx.x;
    const int mg  = tid >> 3;
    const int ng  = tid & 7;
    const int wk  = tid >> 3;
    const int wn  = (tid & 7) * 8;

    const float* Arow = A + (size_t)(m0 + tid) * K;

    float acc[8][8];
    #pragma unroll
    for (int i = 0; i < 8; i++)
        #pragma unroll
        for (int j = 0; j < 8; j++) acc[i][j] = 0.f;

    for (int k0 = 0; k0 < K; k0 += BK) {
        #pragma unroll
        for (int q = 0; q < 16; q++) {
            int k = k0 + q;
            As[q][tid] = (k < K) ? Arow[k] : 0.f;
        }
        {
            int k = k0 + wk, n = n0 + wn;
            float t[8];
            #pragma unroll
            for (int j = 0; j < 8; j++)
                t[j] = (k < K && n + j < N) ? W[(size_t)k * N + n + j] : 0.f;
            *(float4*)&Ws[wk][wn]     = make_float4(t[0], t[1], t[2], t[3]);
            *(float4*)&Ws[wk][wn + 4] = make_float4(t[4], t[5], t[6], t[7]);
        }
        __syncthreads();
        #pragma unroll
        for (int kk = 0; kk < BK; kk++) {
            float4 a0 = *(const float4*)&As[kk][mg * 8];
            float4 a1 = *(const float4*)&As[kk][mg * 8 + 4];
            float4 b0 = *(const float4*)&Ws[kk][ng * 4];
            float4 b1 = *(const float4*)&Ws[kk][32 + ng * 4];
            float ar[8] = {a0.x,a0.y,a0.z,a0.w,a1.x,a1.y,a1.z,a1.w};
            float br[8] = {b0.x,b0.y,b0.z,b0.w,b1.x,b1.y,b1.z,b1.w};
            #pragma unroll
            for (int i = 0; i < 8; i++)
                #pragma unroll
                for (int j = 0; j < 8; j++)
                    acc[i][j] = fmaf(ar[i], br[j], acc[i][j]);
        }
        __syncthreads();
    }

    float colSum[8], colSq[8];
    #pragma unroll
    for (int j = 0; j < 8; j++) { colSum[j] = 0.f; colSq[j] = 0.f; }

    const int cA = n0 + ng * 4;
    const int cB = n0 + 32 + ng * 4;
    float bvA[4], bvB[4];
    #pragma unroll
    for (int j = 0; j < 4; j++) {
        bvA[j] = (cA + j < N) ? bias[cA + j] : 0.f;
        bvB[j] = (cB + j < N) ? bias[cB + j] : 0.f;
    }

    #pragma unroll
    for (int i = 0; i < 8; i++) {
        const int m = m0 + mg * 8 + i;
        const size_t rb = (size_t)m * KP_H;
        float vA[4], vB[4];
        #pragma unroll
        for (int j = 0; j < 4; j++) {
            float cc = fmaxf(acc[i][j] + bvA[j], 0.f);
            vA[j] = cc;
            if (cA + j < N) { colSum[j] += cc; colSq[j] += cc * cc; }
            cc = fmaxf(acc[i][4 + j] + bvB[j], 0.f);
            vB[j] = cc;
            if (cB + j < N) { colSum[4 + j] += cc; colSq[4 + j] += cc * cc; }
        }
        // split-store quads (N=300 multiple of 4 -> whole quad valid or not)
        if (cA < N) {
            __nv_bfloat16 h0,l0,h1,l1;
            #pragma unroll
            for (int p = 0; p < 2; p++) {
                bsplit(vA[2*p], h0, l0); bsplit(vA[2*p+1], h1, l1);
                *(u32*)&g_hh[rb + cA + 2*p] =
                    (u32)__bfloat16_as_ushort(h0) | ((u32)__bfloat16_as_ushort(h1) << 16);
                *(u32*)&g_hl[rb + cA + 2*p] =
                    (u32)__bfloat16_as_ushort(l0) | ((u32)__bfloat16_as_ushort(l1) << 16);
            }
        }
        if (cB < N) {
            __nv_bfloat16 h0,l0,h1,l1;
            #pragma unroll
            for (int p = 0; p < 2; p++) {
                bsplit(vB[2*p], h0, l0); bsplit(vB[2*p+1], h1, l1);
                *(u32*)&g_hh[rb + cB + 2*p] =
                    (u32)__bfloat16_as_ushort(h0) | ((u32)__bfloat16_as_ushort(h1) << 16);
                *(u32*)&g_hl[rb + cB + 2*p] =
                    (u32)__bfloat16_as_ushort(l0) | ((u32)__bfloat16_as_ushort(l1) << 16);
            }
        }
    }

    if (tid < BN) { sSum[tid] = 0.f; sSq[tid] = 0.f; }
    __syncthreads();
    #pragma unroll
    for (int j = 0; j < 4; j++) {
        atomicAdd(&sSum[ng * 4 + j],      colSum[j]);
        atomicAdd(&sSq [ng * 4 + j],      colSq [j]);
        atomicAdd(&sSum[32 + ng * 4 + j], colSum[4 + j]);
        atomicAdd(&sSq [32 + ng * 4 + j], colSq [4 + j]);
    }
    __syncthreads();
    if (tid < BN) {
        int n = n0 + tid;
        if (n < N) {
            atomicAdd(&g_sum[n], sSum[tid]);
            atomicAdd(&g_sq [n], sSq [tid]);
        }
    }
}

// ---------------- small scalar GEMM: a = BN(ap) @ Wa2 + ba2 (N=63,K=150) ----
__global__ void __launch_bounds__(256, 4)
sgemm_kernel(const float* __restrict__ W, const float* __restrict__ bias,
             int normOff, int N, int K)
{
    const int BN = 64, BK = 8, TM = 8, TN = 4;
    __shared__ float As[BK][128];
    __shared__ float Ws[BK][BN];

    const int m0  = blockIdx.y * 128;
    const int n0  = blockIdx.x * BN;
    const int tid = threadIdx.x;
    const int tx  = tid & 15;
    const int ty  = tid >> 4;

    float acc[TM][TN];
    #pragma unroll
    for (int i = 0; i < TM; i++)
        #pragma unroll
        for (int j = 0; j < TN; j++) acc[i][j] = 0.f;

    for (int k0 = 0; k0 < K; k0 += BK) {
        #pragma unroll
        for (int i = 0; i < 4; i++) {
            int idx = tid + i * 256;
            int mm  = idx >> 3;
            int kk  = idx & 7;
            int k   = k0 + kk;
            float v = 0.f;
            if (k < K) {
                v = g_ap[(size_t)(m0 + mm) * K + k];
                v = fmaf(v, g_scale[normOff + k], g_shift[normOff + k]);
            }
            As[kk][mm] = v;
        }
        #pragma unroll
        for (int i = 0; i < 2; i++) {
            int idx = tid + i * 256;
            int kk  = idx >> 6;
            int nn  = idx & 63;
            int k   = k0 + kk, n = n0 + nn;
            Ws[kk][nn] = (k < K && n < N) ? W[(size_t)k * N + n] : 0.f;
        }
        __syncthreads();
        #pragma unroll
        for (int kk = 0; kk < BK; kk++) {
            float ar[TM], br[TN];
            #pragma unroll
            for (int i = 0; i < TM; i++) ar[i] = As[kk][ty * TM + i];
            #pragma unroll
            for (int j = 0; j < TN; j++) br[j] = Ws[kk][tx * TN + j];
            #pragma unroll
            for (int i = 0; i < TM; i++)
                #pragma unroll
                for (int j = 0; j < TN; j++)
                    acc[i][j] = fmaf(ar[i], br[j], acc[i][j]);
        }
        __syncthreads();
    }

    #pragma unroll
    for (int j = 0; j < TN; j++) {
        int n = n0 + tx * TN + j;
        if (n < N) {
            float bv = bias[n];
            #pragma unroll
            for (int i = 0; i < TM; i++)
                g_a[(size_t)(m0 + ty * TM + i) * N + n] = acc[i][j] + bv;
        }
    }
}

// ---------------- Toeplitz epilogue (REAL parts only) -----------------------
__global__ void __launch_bounds__(256)
toeplitz_real_kernel(float* __restrict__ out,
                     size_t offB, size_t offC, size_t budgetElems)
{
    __shared__ float sre[8][32];
    const int warp = threadIdx.x >> 5;
    const int lane = threadIdx.x & 31;
    const int row  = blockIdx.x * 8 + warp;

    const float* ar = g_a + (size_t)row * 63;
    float v0 = ar[lane];
    float a0 = fminf(expf(__shfl_sync(0xffffffffu, v0, 0)), 500.f);

    float re = (lane == 0) ? a0 : (0.022f * a0 * tanhf(v0));
    sre[warp][lane] = re;
    __syncwarp();

    const size_t rbase = (size_t)row * 1024 + lane;
    #pragma unroll
    for (int i = 0; i < 32; i++) {
        int d = i - lane;
        float b = (d >= 0) ? sre[warp][d]      : 0.f;
        float c = (d >= 1) ? sre[warp][32 - d] : 0.f;
        size_t ib = offB + rbase + (size_t)i * 32;
        size_t ic = offC + rbase + (size_t)i * 32;
        if (ib < budgetElems) out[ib] = b;
        if (ic < budgetElems) out[ic] = c;
    }
}

// ---------------- launch -----------------------------------------------------
extern "C" void kernel_launch(void* const* d_in, const int* in_sizes, int n_in,
                              void* d_out, int out_size)
{
    if (n_in < 17) return;

    const float* z   = (const float*)d_in[0];
    const float* W1  = (const float*)d_in[1];
    const float* b1  = (const float*)d_in[2];
    const float* g1  = (const float*)d_in[3];
    const float* be1 = (const float*)d_in[4];
    const float* W2  = (const float*)d_in[5];
    const float* b2  = (const float*)d_in[6];
    const float* g2  = (const float*)d_in[7];
    const float* be2 = (const float*)d_in[8];
    const float* W3  = (const float*)d_in[9];
    const float* b3  = (const float*)d_in[10];
    const float* Wa1 = (const float*)d_in[11];
    const float* ba1 = (const float*)d_in[12];
    const float* ga  = (const float*)d_in[13];
    const float* bea = (const float*)d_in[14];
    const float* Wa2 = (const float*)d_in[15];
    const float* ba2 = (const float*)d_in[16];

    long long Braw = (long long)in_sizes[0] / 24;
    if (Braw > BATCH) Braw = BATCH;
    Braw -= (Braw % 128);
    if (Braw <= 0) return;
    const int B = (int)Braw;
    const long long LB = (long long)B;

    float* out = (float*)d_out;
    const float invB = 1.0f / (float)B;
    const size_t budgetBytes = (size_t)out_size * 4;
    const size_t budgetElems = (size_t)out_size;
    const int mB = B / 128;

    zero_stats_kernel<<<4, 256>>>();
    padzero_kernel<<<(B * 36 + 255) / 256, 256>>>(B);

    // 1. h = relu(z @ W1 + b1) -> bf16 split planes + stats@0
    fgemm1_kernel<<<dim3(5, mB), 128>>>(z, W1, b1, 300, 24);

    finalize_stats_kernel<<<2, 256>>>(g1, be1, 0, 300, invB);

    // fold BN1 into W2 / Wa1 (+ bias corrections)
    fold_kernel<<<400, 128>>>(W2,  b2,  0, 400, 300, KP_H, 4, 2);
    fold_kernel<<<150, 128>>>(Wa1, ba1, 0, 150, 300, KP_H, 6, 3);

    // 3. m = relu(h @ W2' + b2') -> split planes + stats@300   [tensor]
    bgemm_kernel<true, true, 2><<<dim3(4, mB), 256>>>(
        0, KP_H, 4, 2, nullptr, 0, 300, 400, 300);

    // 4. ap = relu(h @ Wa1' + bpa) -> f32 g_ap + stats@700     [tensor]
    bgemm_kernel<true, true, 1><<<dim3(2, mB), 256>>>(
        0, KP_H, 6, 3, nullptr, 0, 700, 150, 300);

    finalize_stats_kernel<<<2, 256>>>(g2, be2, 300, 400, invB);
    finalize_stats_kernel<<<1, 256>>>(ga, bea, 700, 150, invB);

    // fold BN2 into W3
    fold_kernel<<<1024, 128>>>(W3, b3, 300, 1024, 400, KP_M, 8, 4);

    // 6. mu = m @ W3' + bp3 -> out                             [tensor]
    bgemm_kernel<false, false, 0><<<dim3(8, mB), 256>>>(
        2, KP_M, 8, 4, out, budgetBytes, 0, 1024, 400);

    // 7. a = BN(ap) @ Wa2 + ba2 -> g_a
    sgemm_kernel<<<dim3(1, mB), 256>>>(Wa2, ba2, 700, 63, 150);

    // 8. Toeplitz real parts
    toeplitz_real_kernel<<<B / 8, 256>>>(out, (size_t)LB * 1024,
                                         (size_t)LB * 2048, budgetElems);
}

// round 13
// speedup vs baseline: 1.9031x; 1.1988x over previous
#include <cuda_runtime.h>
#include <cuda_bf16.h>
#include <math.h>

#define BATCH 32768
#define EPS   1e-5f
#define KP_H  320     // padded K for h planes (K=300)
#define KP_M  416     // padded K for m planes (K=400)

typedef unsigned int  u32;
typedef unsigned short u16;
typedef unsigned long long u64;

// ---------------- scratch (device globals) -----------------------------------
__device__ __nv_bfloat16 g_hh[(size_t)BATCH * KP_H], g_hl[(size_t)BATCH * KP_H];
__device__ __nv_bfloat16 g_mh[(size_t)BATCH * KP_M], g_ml[(size_t)BATCH * KP_M];
__device__ float g_ap[(size_t)BATCH * 150];
__device__ float g_a [(size_t)BATCH * 63];

__device__ __nv_bfloat16 g_W2h [400  * KP_H], g_W2l [400  * KP_H];
__device__ __nv_bfloat16 g_Wa1h[150  * KP_H], g_Wa1l[150  * KP_H];
__device__ __nv_bfloat16 g_W3h [1024 * KP_M], g_W3l [1024 * KP_M];
__device__ float g_bp2[400], g_bpa[150], g_bp3[1024];

#define STATS_TOTAL 860
__device__ float g_sum  [STATS_TOTAL];
__device__ float g_sq   [STATS_TOTAL];
__device__ float g_scale[STATS_TOTAL];
__device__ float g_shift[STATS_TOTAL];

__device__ __forceinline__ __nv_bfloat16* sel_bf(int s) {
    switch (s) {
        case 0: return g_hh;   case 1: return g_hl;
        case 2: return g_mh;   case 3: return g_ml;
        case 4: return g_W2h;  case 5: return g_W2l;
        case 6: return g_Wa1h; case 7: return g_Wa1l;
        case 8: return g_W3h;  case 9: return g_W3l;
    }
    return nullptr;
}
__device__ __forceinline__ float* sel_f(int s) {
    switch (s) {
        case 2: return g_bp2;  case 3: return g_bpa;  case 4: return g_bp3;
    }
    return nullptr;
}

__global__ void zero_stats_kernel() {
    int i = blockIdx.x * blockDim.x + threadIdx.x;
    if (i < STATS_TOTAL) { g_sum[i] = 0.f; g_sq[i] = 0.f; }
}

// zero the k-padding columns of the activation planes
__global__ void padzero_kernel(int B) {
    int idx = blockIdx.x * blockDim.x + threadIdx.x;
    const __nv_bfloat16 z = __float2bfloat16(0.f);
    if (idx < B * 20) {
        int r = idx / 20, c = idx % 20;
        g_hh[(size_t)r * KP_H + 300 + c] = z;
        g_hl[(size_t)r * KP_H + 300 + c] = z;
    } else {
        idx -= B * 20;
        if (idx < B * 16) {
            int r = idx / 16, c = idx % 16;
            g_mh[(size_t)r * KP_M + 400 + c] = z;
            g_ml[(size_t)r * KP_M + 400 + c] = z;
        }
    }
}

__global__ void finalize_stats_kernel(const float* __restrict__ g,
                                      const float* __restrict__ be,
                                      int off, int n, float invB) {
    int i = blockIdx.x * blockDim.x + threadIdx.x;
    if (i < n) {
        float mean = g_sum[off + i] * invB;
        float var  = g_sq [off + i] * invB - mean * mean;
        float s    = g[i] * rsqrtf(var + EPS);
        g_scale[off + i] = s;
        g_shift[off + i] = be[i] - mean * s;
    }
}

// ---------------- bf16 split helper ------------------------------------------
__device__ __forceinline__ void bsplit(float v, __nv_bfloat16& h, __nv_bfloat16& l) {
    h = __float2bfloat16(v);
    l = __float2bfloat16(v - __bfloat162float(h));
}

// ---------------- weight fold -------------------------------------------------
__global__ void __launch_bounds__(128)
fold_kernel(const float* __restrict__ W, const float* __restrict__ bias,
            int scOff, int N, int K, int Kp, int wSel, int bpSel)
{
    __shared__ float red[128];
    const int n = blockIdx.x;
    const int tid = threadIdx.x;
    __nv_bfloat16* Wh = sel_bf(wSel);
    __nv_bfloat16* Wl = sel_bf(wSel + 1);
    float* bp = sel_f(bpSel);

    float acc = 0.f;
    for (int k = tid; k < Kp; k += 128) {
        float w = 0.f, sc = 0.f, sh = 0.f;
        if (k < K) {
            w  = W[(size_t)k * N + n];
            sc = g_scale[scOff + k];
            sh = g_shift[scOff + k];
        }
        float wp = w * sc;
        __nv_bfloat16 h, l;
        bsplit(wp, h, l);
        Wh[(size_t)n * Kp + k] = h;
        Wl[(size_t)n * Kp + k] = l;
        acc += sh * w;
    }
    red[tid] = acc;
    __syncthreads();
    #pragma unroll
    for (int s = 64; s > 0; s >>= 1) {
        if (tid < s) red[tid] += red[tid + s];
        __syncthreads();
    }
    if (tid == 0) bp[n] = bias[n] + red[0];
}

// ---------------- mma / ldmatrix wrappers -------------------------------------
__device__ __forceinline__ void mma_bf16(float c[4], const u32 a[4],
                                         u32 b0, u32 b1) {
    asm volatile("mma.sync.aligned.m16n8k16.row.col.f32.bf16.bf16.f32 "
        "{%0,%1,%2,%3}, {%4,%5,%6,%7}, {%8,%9}, {%0,%1,%2,%3};"
        : "+f"(c[0]), "+f"(c[1]), "+f"(c[2]), "+f"(c[3])
        : "r"(a[0]), "r"(a[1]), "r"(a[2]), "r"(a[3]), "r"(b0), "r"(b1));
}
__device__ __forceinline__ void ldsm_x4(u32& r0, u32& r1, u32& r2, u32& r3, u32 addr) {
    asm volatile("ldmatrix.sync.aligned.m8n8.x4.shared.b16 {%0,%1,%2,%3}, [%4];"
        : "=r"(r0), "=r"(r1), "=r"(r2), "=r"(r3) : "r"(addr));
}

// ============================================================================
// bf16-split tensor GEMM with register-prefetch double buffering.
// BM=128, BN=128, BK=32, 256 thr (8 warps, 2m x 4n), warp tile 64x32.
// OUTMODE: 0 = f32 to Cext (guarded), 1 = f32 to g_ap, 2 = split to g_m*
// ============================================================================
template<bool RELU, bool STATS, int OUTMODE>
__global__ void __launch_bounds__(256)
bgemm_kernel(int aSel, int aKP, int bSel, int bpSel,
             float* __restrict__ Cext, size_t cBudget,
             int statOff, int N, int K)
{
    __shared__ __align__(16) __nv_bfloat16 sAh[128 * 40], sAl[128 * 40];
    __shared__ __align__(16) __nv_bfloat16 sBh[128 * 40], sBl[128 * 40];
    __shared__ float sSum[128], sSq[128];

    const __nv_bfloat16* Ah = sel_bf(aSel);
    const __nv_bfloat16* Al = sel_bf(aSel + 1);
    const __nv_bfloat16* Bh = sel_bf(bSel);
    const __nv_bfloat16* Bl = sel_bf(bSel + 1);
    const float* bp = sel_f(bpSel);

    const int m0 = blockIdx.y * 128, n0 = blockIdx.x * 128;
    const int tid = threadIdx.x, wid = tid >> 5, lane = tid & 31;
    const int g = lane >> 2, tg = lane & 3;
    const int wm = (wid >> 2) * 64, wn = (wid & 3) * 32;

    if (tid < 128) { sSum[tid] = 0.f; sSq[tid] = 0.f; }

    const int srow = tid >> 1, shalf = tid & 1;
    const size_t aOff = (size_t)(m0 + srow) * aKP + shalf * 16;
    const int bRow = n0 + srow;
    const size_t bOff = (size_t)bRow * aKP + shalf * 16;
    const int sOff = srow * 40 + shalf * 16;

    const u32 baseAh = (u32)__cvta_generic_to_shared(sAh);
    const u32 baseAl = (u32)__cvta_generic_to_shared(sAl);
    const u32 baseBh = (u32)__cvta_generic_to_shared(sBh);
    const u32 baseBl = (u32)__cvta_generic_to_shared(sBl);
    const u32 aLOff = (u32)((wm + (lane & 15)) * 80 + (lane >> 4) * 16);
    const u32 bLOff = (u32)((wn + ((lane >> 4) & 1) * 8 + (lane & 7)) * 80
                            + ((lane >> 3) & 1) * 16);

    float c[4][4][4];
    #pragma unroll
    for (int t = 0; t < 4; t++)
        #pragma unroll
        for (int u = 0; u < 4; u++)
            #pragma unroll
            for (int v = 0; v < 4; v++) c[t][u][v] = 0.f;

    const int nT = (K + 31) / 32;
    const uint4 z4 = make_uint4(0, 0, 0, 0);

    // prefetch registers (tile t+1)
    uint4 pa0, pa1, pa2, pa3, pb0, pb1, pb2, pb3;

    // prologue: load tile 0 into regs, store to smem
    {
        const uint4* p = (const uint4*)(Ah + aOff);
        pa0 = p[0]; pa1 = p[1];
        const uint4* q = (const uint4*)(Al + aOff);
        pa2 = q[0]; pa3 = q[1];
        pb0 = z4; pb1 = z4; pb2 = z4; pb3 = z4;
        if (bRow < N) {
            const uint4* r = (const uint4*)(Bh + bOff);
            pb0 = r[0]; pb1 = r[1];
            const uint4* s = (const uint4*)(Bl + bOff);
            pb2 = s[0]; pb3 = s[1];
        }
        *(uint4*)&sAh[sOff] = pa0; *(uint4*)&sAh[sOff + 8] = pa1;
        *(uint4*)&sAl[sOff] = pa2; *(uint4*)&sAl[sOff + 8] = pa3;
        *(uint4*)&sBh[sOff] = pb0; *(uint4*)&sBh[sOff + 8] = pb1;
        *(uint4*)&sBl[sOff] = pb2; *(uint4*)&sBl[sOff + 8] = pb3;
    }
    __syncthreads();

    for (int t0 = 0; t0 < nT; t0++) {
        const bool more = (t0 + 1 < nT);
        // ---- prefetch next tile into registers (overlaps mma below) --------
        if (more) {
            const int k1 = (t0 + 1) * 32;
            const uint4* p = (const uint4*)(Ah + aOff + k1);
            pa0 = p[0]; pa1 = p[1];
            const uint4* q = (const uint4*)(Al + aOff + k1);
            pa2 = q[0]; pa3 = q[1];
            pb0 = z4; pb1 = z4; pb2 = z4; pb3 = z4;
            if (bRow < N) {
                const uint4* r = (const uint4*)(Bh + bOff + k1);
                pb0 = r[0]; pb1 = r[1];
                const uint4* s = (const uint4*)(Bl + bOff + k1);
                pb2 = s[0]; pb3 = s[1];
            }
        }

        // ---- compute current tile from smem --------------------------------
        #pragma unroll
        for (int ks = 0; ks < 32; ks += 16) {
            u32 ah[4][4], al[4][4], bh[4][2], bl[4][2];
            #pragma unroll
            for (int t = 0; t < 4; t++) {
                u32 off = (u32)(t * 16 * 80 + ks * 2) + aLOff;
                ldsm_x4(ah[t][0], ah[t][1], ah[t][2], ah[t][3], baseAh + off);
                ldsm_x4(al[t][0], al[t][1], al[t][2], al[t][3], baseAl + off);
            }
            #pragma unroll
            for (int up = 0; up < 2; up++) {
                u32 off = (u32)(up * 16 * 80 + ks * 2) + bLOff;
                ldsm_x4(bh[2*up][0], bh[2*up][1], bh[2*up+1][0], bh[2*up+1][1],
                        baseBh + off);
                ldsm_x4(bl[2*up][0], bl[2*up][1], bl[2*up+1][0], bl[2*up+1][1],
                        baseBl + off);
            }
            #pragma unroll
            for (int t = 0; t < 4; t++)
                #pragma unroll
                for (int u = 0; u < 4; u++)
                    mma_bf16(c[t][u], ah[t], bh[u][0], bh[u][1]);
            #pragma unroll
            for (int t = 0; t < 4; t++)
                #pragma unroll
                for (int u = 0; u < 4; u++)
                    mma_bf16(c[t][u], al[t], bh[u][0], bh[u][1]);
            #pragma unroll
            for (int t = 0; t < 4; t++)
                #pragma unroll
                for (int u = 0; u < 4; u++)
                    mma_bf16(c[t][u], ah[t], bl[u][0], bl[u][1]);
        }
        __syncthreads();

        // ---- store prefetched tile ------------------------------------------
        if (more) {
            *(uint4*)&sAh[sOff] = pa0; *(uint4*)&sAh[sOff + 8] = pa1;
            *(uint4*)&sAl[sOff] = pa2; *(uint4*)&sAl[sOff + 8] = pa3;
            *(uint4*)&sBh[sOff] = pb0; *(uint4*)&sBh[sOff + 8] = pb1;
            *(uint4*)&sBl[sOff] = pb2; *(uint4*)&sBl[sOff + 8] = pb3;
            __syncthreads();
        }
    }

    // ---- epilogue -----------------------------------------------------------
    float colS[8], colQ[8];
    #pragma unroll
    for (int j = 0; j < 8; j++) { colS[j] = 0.f; colQ[j] = 0.f; }

    #pragma unroll
    for (int t = 0; t < 4; t++) {
        const int r0 = m0 + wm + t * 16 + g;
        const int r1 = r0 + 8;
        #pragma unroll
        for (int u = 0; u < 4; u++) {
            const int colb = n0 + wn + u * 8 + 2 * tg;
            if (colb >= N) continue;
            const float bv0 = bp[colb];
            const float bv1 = (colb + 1 < N) ? bp[colb + 1] : 0.f;
            float x0 = c[t][u][0] + bv0, x1 = c[t][u][1] + bv1;
            float x2 = c[t][u][2] + bv0, x3 = c[t][u][3] + bv1;
            if (RELU) {
                x0 = fmaxf(x0, 0.f); x1 = fmaxf(x1, 0.f);
                x2 = fmaxf(x2, 0.f); x3 = fmaxf(x3, 0.f);
            }
            if (OUTMODE == 0) {
                const size_t i0 = (size_t)r0 * N + colb;
                const size_t i1 = (size_t)r1 * N + colb;
                if (colb + 1 < N) {
                    if ((i0 + 2) * 4 <= cBudget) *(float2*)(Cext + i0) = make_float2(x0, x1);
                    if ((i1 + 2) * 4 <= cBudget) *(float2*)(Cext + i1) = make_float2(x2, x3);
                } else {
                    if ((i0 + 1) * 4 <= cBudget) Cext[i0] = x0;
                    if ((i1 + 1) * 4 <= cBudget) Cext[i1] = x2;
                }
            } else if (OUTMODE == 1) {
                if (colb + 1 < N) {
                    *(float2*)(g_ap + (size_t)r0 * N + colb) = make_float2(x0, x1);
                    *(float2*)(g_ap + (size_t)r1 * N + colb) = make_float2(x2, x3);
                } else {
                    g_ap[(size_t)r0 * N + colb] = x0;
                    g_ap[(size_t)r1 * N + colb] = x2;
                }
            } else {
                __nv_bfloat16 h0, l0, h1, l1;
                bsplit(x0, h0, l0); bsplit(x1, h1, l1);
                *(u32*)&g_mh[(size_t)r0 * KP_M + colb] =
                    (u32)__bfloat16_as_ushort(h0) | ((u32)__bfloat16_as_ushort(h1) << 16);
                *(u32*)&g_ml[(size_t)r0 * KP_M + colb] =
                    (u32)__bfloat16_as_ushort(l0) | ((u32)__bfloat16_as_ushort(l1) << 16);
                bsplit(x2, h0, l0); bsplit(x3, h1, l1);
                *(u32*)&g_mh[(size_t)r1 * KP_M + colb] =
                    (u32)__bfloat16_as_ushort(h0) | ((u32)__bfloat16_as_ushort(h1) << 16);
                *(u32*)&g_ml[(size_t)r1 * KP_M + colb] =
                    (u32)__bfloat16_as_ushort(l0) | ((u32)__bfloat16_as_ushort(l1) << 16);
            }
            if (STATS) {
                const int j = u * 2;
                colS[j] += x0 + x2; colQ[j] += x0 * x0 + x2 * x2;
                if (colb + 1 < N) { colS[j+1] += x1 + x3; colQ[j+1] += x1*x1 + x3*x3; }
            }
        }
    }

    if (STATS) {
        #pragma unroll
        for (int u = 0; u < 4; u++)
            #pragma unroll
            for (int p = 0; p < 2; p++) {
                int ln = wn + u * 8 + 2 * tg + p;
                atomicAdd(&sSum[ln], colS[u * 2 + p]);
                atomicAdd(&sSq [ln], colQ[u * 2 + p]);
            }
        __syncthreads();
        if (tid < 128) {
            int n = n0 + tid;
            if (n < N) {
                atomicAdd(&g_sum[statOff + n], sSum[tid]);
                atomicAdd(&g_sq [statOff + n], sSq [tid]);
            }
        }
    }
}

// ============================================================================
// Layer-1 GEMM (K=24, N=300): fp32 compute, writes h as bf16 split planes.
// ============================================================================
__global__ void __launch_bounds__(128)
fgemm1_kernel(const float* __restrict__ A, const float* __restrict__ W,
              const float* __restrict__ bias, int N, int K)
{
    const int BN = 64, BK = 16;
    __shared__ __align__(16) float As[BK][128];
    __shared__ __align__(16) float Ws[BK][BN];
    __shared__ float sSum[BN], sSq[BN];

    const int m0  = blockIdx.y * 128;
    const int n0  = blockIdx.x * BN;
    const int tid = threadIdx.x;
    const int mg  = tid >> 3;
    const int ng  = tid & 7;
    const int wk  = tid >> 3;
    const int wn  = (tid & 7) * 8;

    const float* Arow = A + (size_t)(m0 + tid) * K;

    float acc[8][8];
    #pragma unroll
    for (int i = 0; i < 8; i++)
        #pragma unroll
        for (int j = 0; j < 8; j++) acc[i][j] = 0.f;

    for (int k0 = 0; k0 < K; k0 += BK) {
        #pragma unroll
        for (int q = 0; q < 16; q++) {
            int k = k0 + q;
            As[q][tid] = (k < K) ? Arow[k] : 0.f;
        }
        {
            int k = k0 + wk, n = n0 + wn;
            float t[8];
            #pragma unroll
            for (int j = 0; j < 8; j++)
                t[j] = (k < K && n + j < N) ? W[(size_t)k * N + n + j] : 0.f;
            *(float4*)&Ws[wk][wn]     = make_float4(t[0], t[1], t[2], t[3]);
            *(float4*)&Ws[wk][wn + 4] = make_float4(t[4], t[5], t[6], t[7]);
        }
        __syncthreads();
        #pragma unroll
        for (int kk = 0; kk < BK; kk++) {
            float4 a0 = *(const float4*)&As[kk][mg * 8];
            float4 a1 = *(const float4*)&As[kk][mg * 8 + 4];
            float4 b0 = *(const float4*)&Ws[kk][ng * 4];
            float4 b1 = *(const float4*)&Ws[kk][32 + ng * 4];
            float ar[8] = {a0.x,a0.y,a0.z,a0.w,a1.x,a1.y,a1.z,a1.w};
            float br[8] = {b0.x,b0.y,b0.z,b0.w,b1.x,b1.y,b1.z,b1.w};
            #pragma unroll
            for (int i = 0; i < 8; i++)
                #pragma unroll
                for (int j = 0; j < 8; j++)
                    acc[i][j] = fmaf(ar[i], br[j], acc[i][j]);
        }
        __syncthreads();
    }

    float colSum[8], colSq[8];
    #pragma unroll
    for (int j = 0; j < 8; j++) { colSum[j] = 0.f; colSq[j] = 0.f; }

    const int cA = n0 + ng * 4;
    const int cB = n0 + 32 + ng * 4;
    float bvA[4], bvB[4];
    #pragma unroll
    for (int j = 0; j < 4; j++) {
        bvA[j] = (cA + j < N) ? bias[cA + j] : 0.f;
        bvB[j] = (cB + j < N) ? bias[cB + j] : 0.f;
    }

    #pragma unroll
    for (int i = 0; i < 8; i++) {
        const int m = m0 + mg * 8 + i;
        const size_t rb = (size_t)m * KP_H;
        float vA[4], vB[4];
        #pragma unroll
        for (int j = 0; j < 4; j++) {
            float cc = fmaxf(acc[i][j] + bvA[j], 0.f);
            vA[j] = cc;
            if (cA + j < N) { colSum[j] += cc; colSq[j] += cc * cc; }
            cc = fmaxf(acc[i][4 + j] + bvB[j], 0.f);
            vB[j] = cc;
            if (cB + j < N) { colSum[4 + j] += cc; colSq[4 + j] += cc * cc; }
        }
        if (cA < N) {
            __nv_bfloat16 h0,l0,h1,l1;
            #pragma unroll
            for (int p = 0; p < 2; p++) {
                bsplit(vA[2*p], h0, l0); bsplit(vA[2*p+1], h1, l1);
                *(u32*)&g_hh[rb + cA + 2*p] =
                    (u32)__bfloat16_as_ushort(h0) | ((u32)__bfloat16_as_ushort(h1) << 16);
                *(u32*)&g_hl[rb + cA + 2*p] =
                    (u32)__bfloat16_as_ushort(l0) | ((u32)__bfloat16_as_ushort(l1) << 16);
            }
        }
        if (cB < N) {
            __nv_bfloat16 h0,l0,h1,l1;
            #pragma unroll
            for (int p = 0; p < 2; p++) {
                bsplit(vB[2*p], h0, l0); bsplit(vB[2*p+1], h1, l1);
                *(u32*)&g_hh[rb + cB + 2*p] =
                    (u32)__bfloat16_as_ushort(h0) | ((u32)__bfloat16_as_ushort(h1) << 16);
                *(u32*)&g_hl[rb + cB + 2*p] =
                    (u32)__bfloat16_as_ushort(l0) | ((u32)__bfloat16_as_ushort(l1) << 16);
            }
        }
    }

    if (tid < BN) { sSum[tid] = 0.f; sSq[tid] = 0.f; }
    __syncthreads();
    #pragma unroll
    for (int j = 0; j < 4; j++) {
        atomicAdd(&sSum[ng * 4 + j],      colSum[j]);
        atomicAdd(&sSq [ng * 4 + j],      colSq [j]);
        atomicAdd(&sSum[32 + ng * 4 + j], colSum[4 + j]);
        atomicAdd(&sSq [32 + ng * 4 + j], colSq [4 + j]);
    }
    __syncthreads();
    if (tid < BN) {
        int n = n0 + tid;
        if (n < N) {
            atomicAdd(&g_sum[n], sSum[tid]);
            atomicAdd(&g_sq [n], sSq [tid]);
        }
    }
}

// ---------------- small scalar GEMM: a = BN(ap) @ Wa2 + ba2 (N=63,K=150) ----
__global__ void __launch_bounds__(256, 4)
sgemm_kernel(const float* __restrict__ W, const float* __restrict__ bias,
             int normOff, int N, int K)
{
    const int BN = 64, BK = 8, TM = 8, TN = 4;
    __shared__ float As[BK][128];
    __shared__ float Ws[BK][BN];

    const int m0  = blockIdx.y * 128;
    const int n0  = blockIdx.x * BN;
    const int tid = threadIdx.x;
    const int tx  = tid & 15;
    const int ty  = tid >> 4;

    float acc[TM][TN];
    #pragma unroll
    for (int i = 0; i < TM; i++)
        #pragma unroll
        for (int j = 0; j < TN; j++) acc[i][j] = 0.f;

    for (int k0 = 0; k0 < K; k0 += BK) {
        #pragma unroll
        for (int i = 0; i < 4; i++) {
            int idx = tid + i * 256;
            int mm  = idx >> 3;
            int kk  = idx & 7;
            int k   = k0 + kk;
            float v = 0.f;
            if (k < K) {
                v = g_ap[(size_t)(m0 + mm) * K + k];
                v = fmaf(v, g_scale[normOff + k], g_shift[normOff + k]);
            }
            As[kk][mm] = v;
        }
        #pragma unroll
        for (int i = 0; i < 2; i++) {
            int idx = tid + i * 256;
            int kk  = idx >> 6;
            int nn  = idx & 63;
            int k   = k0 + kk, n = n0 + nn;
            Ws[kk][nn] = (k < K && n < N) ? W[(size_t)k * N + n] : 0.f;
        }
        __syncthreads();
        #pragma unroll
        for (int kk = 0; kk < BK; kk++) {
            float ar[TM], br[TN];
            #pragma unroll
            for (int i = 0; i < TM; i++) ar[i] = As[kk][ty * TM + i];
            #pragma unroll
            for (int j = 0; j < TN; j++) br[j] = Ws[kk][tx * TN + j];
            #pragma unroll
            for (int i = 0; i < TM; i++)
                #pragma unroll
                for (int j = 0; j < TN; j++)
                    acc[i][j] = fmaf(ar[i], br[j], acc[i][j]);
        }
        __syncthreads();
    }

    #pragma unroll
    for (int j = 0; j < TN; j++) {
        int n = n0 + tx * TN + j;
        if (n < N) {
            float bv = bias[n];
            #pragma unroll
            for (int i = 0; i < TM; i++)
                g_a[(size_t)(m0 + ty * TM + i) * N + n] = acc[i][j] + bv;
        }
    }
}

// ---------------- Toeplitz epilogue (REAL parts only) -----------------------
__global__ void __launch_bounds__(256)
toeplitz_real_kernel(float* __restrict__ out,
                     size_t offB, size_t offC, size_t budgetElems)
{
    __shared__ float sre[8][32];
    const int warp = threadIdx.x >> 5;
    const int lane = threadIdx.x & 31;
    const int row  = blockIdx.x * 8 + warp;

    const float* ar = g_a + (size_t)row * 63;
    float v0 = ar[lane];
    float a0 = fminf(expf(__shfl_sync(0xffffffffu, v0, 0)), 500.f);

    float re = (lane == 0) ? a0 : (0.022f * a0 * tanhf(v0));
    sre[warp][lane] = re;
    __syncwarp();

    const size_t rbase = (size_t)row * 1024 + lane;
    #pragma unroll
    for (int i = 0; i < 32; i++) {
        int d = i - lane;
        float b = (d >= 0) ? sre[warp][d]      : 0.f;
        float c = (d >= 1) ? sre[warp][32 - d] : 0.f;
        size_t ib = offB + rbase + (size_t)i * 32;
        size_t ic = offC + rbase + (size_t)i * 32;
        if (ib < budgetElems) out[ib] = b;
        if (ic < budgetElems) out[ic] = c;
    }
}

// ---------------- launch -----------------------------------------------------
extern "C" void kernel_launch(void* const* d_in, const int* in_sizes, int n_in,
                              void* d_out, int out_size)
{
    if (n_in < 17) return;

    const float* z   = (const float*)d_in[0];
    const float* W1  = (const float*)d_in[1];
    const float* b1  = (const float*)d_in[2];
    const float* g1  = (const float*)d_in[3];
    const float* be1 = (const float*)d_in[4];
    const float* W2  = (const float*)d_in[5];
    const float* b2  = (const float*)d_in[6];
    const float* g2  = (const float*)d_in[7];
    const float* be2 = (const float*)d_in[8];
    const float* W3  = (const float*)d_in[9];
    const float* b3  = (const float*)d_in[10];
    const float* Wa1 = (const float*)d_in[11];
    const float* ba1 = (const float*)d_in[12];
    const float* ga  = (const float*)d_in[13];
    const float* bea = (const float*)d_in[14];
    const float* Wa2 = (const float*)d_in[15];
    const float* ba2 = (const float*)d_in[16];

    long long Braw = (long long)in_sizes[0] / 24;
    if (Braw > BATCH) Braw = BATCH;
    Braw -= (Braw % 128);
    if (Braw <= 0) return;
    const int B = (int)Braw;
    const long long LB = (long long)B;

    float* out = (float*)d_out;
    const float invB = 1.0f / (float)B;
    const size_t budgetBytes = (size_t)out_size * 4;
    const size_t budgetElems = (size_t)out_size;
    const int mB = B / 128;

    zero_stats_kernel<<<4, 256>>>();
    padzero_kernel<<<(B * 36 + 255) / 256, 256>>>(B);

    // 1. h = relu(z @ W1 + b1) -> bf16 split planes + stats@0
    fgemm1_kernel<<<dim3(5, mB), 128>>>(z, W1, b1, 300, 24);

    finalize_stats_kernel<<<2, 256>>>(g1, be1, 0, 300, invB);

    // fold BN1 into W2 / Wa1 (+ bias corrections)
    fold_kernel<<<400, 128>>>(W2,  b2,  0, 400, 300, KP_H, 4, 2);
    fold_kernel<<<150, 128>>>(Wa1, ba1, 0, 150, 300, KP_H, 6, 3);

    // 3. m = relu(h @ W2' + b2') -> split planes + stats@300   [tensor]
    bgemm_kernel<true, true, 2><<<dim3(4, mB), 256>>>(
        0, KP_H, 4, 2, nullptr, 0, 300, 400, 300);

    // 4. ap = relu(h @ Wa1' + bpa) -> f32 g_ap + stats@700     [tensor]
    bgemm_kernel<true, true, 1><<<dim3(2, mB), 256>>>(
        0, KP_H, 6, 3, nullptr, 0, 700, 150, 300);

    finalize_stats_kernel<<<2, 256>>>(g2, be2, 300, 400, invB);
    finalize_stats_kernel<<<1, 256>>>(ga, bea, 700, 150, invB);

    // fold BN2 into W3
    fold_kernel<<<1024, 128>>>(W3, b3, 300, 1024, 400, KP_M, 8, 4);

    // 6. mu = m @ W3' + bp3 -> out                             [tensor]
    bgemm_kernel<false, false, 0><<<dim3(8, mB), 256>>>(
        2, KP_M, 8, 4, out, budgetBytes, 0, 1024, 400);

    // 7. a = BN(ap) @ Wa2 + ba2 -> g_a
    sgemm_kernel<<<dim3(1, mB), 256>>>(Wa2, ba2, 700, 63, 150);

    // 8. Toeplitz real parts
    toeplitz_real_kernel<<<B / 8, 256>>>(out, (size_t)LB * 1024,
                                         (size_t)LB * 2048, budgetElems);
}

// round 15
// speedup vs baseline: 2.0388x; 1.0713x over previous
#include <cuda_runtime.h>
#include <cuda_bf16.h>
#include <math.h>

#define BATCH 32768
#define EPS   1e-5f
#define KP_H  320     // padded K for h planes (K=300)
#define KP_M  416     // padded K for m planes (K=400)
#define NF    550     // fused layer-2/4 output width (400 + 150)

typedef unsigned int  u32;
typedef unsigned short u16;
typedef unsigned long long u64;

// ---------------- scratch (device globals) -----------------------------------
__device__ __nv_bfloat16 g_hh[(size_t)BATCH * KP_H], g_hl[(size_t)BATCH * KP_H];
__device__ __nv_bfloat16 g_mh[(size_t)BATCH * KP_M], g_ml[(size_t)BATCH * KP_M];
__device__ float g_ap[(size_t)BATCH * 150];
__device__ float g_a [(size_t)BATCH * 63];

// fused W2|Wa1 planes: rows 0..399 = BN1-folded W2, rows 400..549 = folded Wa1
__device__ __nv_bfloat16 g_W2h [552  * KP_H], g_W2l [552  * KP_H];
__device__ __nv_bfloat16 g_W3h [1024 * KP_M], g_W3l [1024 * KP_M];
__device__ float g_bp2[552], g_bp3[1024];

#define STATS_TOTAL 860
__device__ float g_sum  [STATS_TOTAL];
__device__ float g_sq   [STATS_TOTAL];
__device__ float g_scale[STATS_TOTAL];
__device__ float g_shift[STATS_TOTAL];

__device__ __forceinline__ __nv_bfloat16* sel_bf(int s) {
    switch (s) {
        case 0: return g_hh;   case 1: return g_hl;
        case 2: return g_mh;   case 3: return g_ml;
        case 4: return g_W2h;  case 5: return g_W2l;
        case 6: return g_W2h + (size_t)400 * KP_H;
        case 7: return g_W2l + (size_t)400 * KP_H;
        case 8: return g_W3h;  case 9: return g_W3l;
    }
    return nullptr;
}
__device__ __forceinline__ float* sel_f(int s) {
    switch (s) {
        case 2: return g_bp2;  case 3: return g_bp2 + 400;  case 4: return g_bp3;
    }
    return nullptr;
}

__global__ void zero_stats_kernel() {
    int i = blockIdx.x * blockDim.x + threadIdx.x;
    if (i < STATS_TOTAL) { g_sum[i] = 0.f; g_sq[i] = 0.f; }
}

// zero the k-padding columns of the activation planes
__global__ void padzero_kernel(int B) {
    int idx = blockIdx.x * blockDim.x + threadIdx.x;
    const __nv_bfloat16 z = __float2bfloat16(0.f);
    if (idx < B * 20) {
        int r = idx / 20, c = idx % 20;
        g_hh[(size_t)r * KP_H + 300 + c] = z;
        g_hl[(size_t)r * KP_H + 300 + c] = z;
    } else {
        idx -= B * 20;
        if (idx < B * 16) {
            int r = idx / 16, c = idx % 16;
            g_mh[(size_t)r * KP_M + 400 + c] = z;
            g_ml[(size_t)r * KP_M + 400 + c] = z;
        }
    }
}

__global__ void finalize_stats_kernel(const float* __restrict__ g,
                                      const float* __restrict__ be,
                                      int off, int n, float invB) {
    int i = blockIdx.x * blockDim.x + threadIdx.x;
    if (i < n) {
        float mean = g_sum[off + i] * invB;
        float var  = g_sq [off + i] * invB - mean * mean;
        float s    = g[i] * rsqrtf(var + EPS);
        g_scale[off + i] = s;
        g_shift[off + i] = be[i] - mean * s;
    }
}

__device__ __forceinline__ void bsplit(float v, __nv_bfloat16& h, __nv_bfloat16& l) {
    h = __float2bfloat16(v);
    l = __float2bfloat16(v - __bfloat162float(h));
}

// ---------------- weight fold -------------------------------------------------
__global__ void __launch_bounds__(128)
fold_kernel(const float* __restrict__ W, const float* __restrict__ bias,
            int scOff, int N, int K, int Kp, int wSel, int bpSel)
{
    __shared__ float red[128];
    const int n = blockIdx.x;
    const int tid = threadIdx.x;
    __nv_bfloat16* Wh = sel_bf(wSel);
    __nv_bfloat16* Wl = sel_bf(wSel + 1);
    float* bp = sel_f(bpSel);

    float acc = 0.f;
    for (int k = tid; k < Kp; k += 128) {
        float w = 0.f, sc = 0.f, sh = 0.f;
        if (k < K) {
            w  = W[(size_t)k * N + n];
            sc = g_scale[scOff + k];
            sh = g_shift[scOff + k];
        }
        float wp = w * sc;
        __nv_bfloat16 h, l;
        bsplit(wp, h, l);
        Wh[(size_t)n * Kp + k] = h;
        Wl[(size_t)n * Kp + k] = l;
        acc += sh * w;
    }
    red[tid] = acc;
    __syncthreads();
    #pragma unroll
    for (int s = 64; s > 0; s >>= 1) {
        if (tid < s) red[tid] += red[tid + s];
        __syncthreads();
    }
    if (tid == 0) bp[n] = bias[n] + red[0];
}

// ---------------- mma / ldmatrix wrappers -------------------------------------
__device__ __forceinline__ void mma_bf16(float c[4], const u32 a[4],
                                         u32 b0, u32 b1) {
    asm volatile("mma.sync.aligned.m16n8k16.row.col.f32.bf16.bf16.f32 "
        "{%0,%1,%2,%3}, {%4,%5,%6,%7}, {%8,%9}, {%0,%1,%2,%3};"
        : "+f"(c[0]), "+f"(c[1]), "+f"(c[2]), "+f"(c[3])
        : "r"(a[0]), "r"(a[1]), "r"(a[2]), "r"(a[3]), "r"(b0), "r"(b1));
}
__device__ __forceinline__ void ldsm_x4(u32& r0, u32& r1, u32& r2, u32& r3, u32 addr) {
    asm volatile("ldmatrix.sync.aligned.m8n8.x4.shared.b16 {%0,%1,%2,%3}, [%4];"
        : "=r"(r0), "=r"(r1), "=r"(r2), "=r"(r3) : "r"(addr));
}

// ============================================================================
// bf16-split tensor GEMM with register-prefetch double buffering.
// BM=128, BN=128, BK=32, 256 thr (8 warps, 2m x 4n), warp tile 64x32.
// OUTMODE: 0 = f32 to Cext (guarded), 2 = split to g_m planes,
//          3 = FUSED: col<400 -> split g_m planes, col>=400 -> f32 g_ap
// ============================================================================
template<bool RELU, bool STATS, int OUTMODE>
__global__ void __launch_bounds__(256)
bgemm_kernel(int aSel, int aKP, int bSel, int bpSel,
             float* __restrict__ Cext, size_t cBudget,
             int statOff, int N, int K)
{
    __shared__ __align__(16) __nv_bfloat16 sAh[128 * 40], sAl[128 * 40];
    __shared__ __align__(16) __nv_bfloat16 sBh[128 * 40], sBl[128 * 40];
    __shared__ float sSum[128], sSq[128];

    const __nv_bfloat16* Ah = sel_bf(aSel);
    const __nv_bfloat16* Al = sel_bf(aSel + 1);
    const __nv_bfloat16* Bh = sel_bf(bSel);
    const __nv_bfloat16* Bl = sel_bf(bSel + 1);
    const float* bp = sel_f(bpSel);

    const int m0 = blockIdx.y * 128, n0 = blockIdx.x * 128;
    const int tid = threadIdx.x, wid = tid >> 5, lane = tid & 31;
    const int g = lane >> 2, tg = lane & 3;
    const int wm = (wid >> 2) * 64, wn = (wid & 3) * 32;

    if (tid < 128) { sSum[tid] = 0.f; sSq[tid] = 0.f; }

    const int srow = tid >> 1, shalf = tid & 1;
    const size_t aOff = (size_t)(m0 + srow) * aKP + shalf * 16;
    const int bRow = n0 + srow;
    const size_t bOff = (size_t)bRow * aKP + shalf * 16;
    const int sOff = srow * 40 + shalf * 16;

    const u32 baseAh = (u32)__cvta_generic_to_shared(sAh);
    const u32 baseAl = (u32)__cvta_generic_to_shared(sAl);
    const u32 baseBh = (u32)__cvta_generic_to_shared(sBh);
    const u32 baseBl = (u32)__cvta_generic_to_shared(sBl);
    const u32 aLOff = (u32)((wm + (lane & 15)) * 80 + (lane >> 4) * 16);
    const u32 bLOff = (u32)((wn + ((lane >> 4) & 1) * 8 + (lane & 7)) * 80
                            + ((lane >> 3) & 1) * 16);

    float c[4][4][4];
    #pragma unroll
    for (int t = 0; t < 4; t++)
        #pragma unroll
        for (int u = 0; u < 4; u++)
            #pragma unroll
            for (int v = 0; v < 4; v++) c[t][u][v] = 0.f;

    const int nT = (K + 31) / 32;
    const uint4 z4 = make_uint4(0, 0, 0, 0);

    uint4 pa0, pa1, pa2, pa3, pb0, pb1, pb2, pb3;

    // prologue: load tile 0 into regs, store to smem
    {
        const uint4* p = (const uint4*)(Ah + aOff);
        pa0 = p[0]; pa1 = p[1];
        const uint4* q = (const uint4*)(Al + aOff);
        pa2 = q[0]; pa3 = q[1];
        pb0 = z4; pb1 = z4; pb2 = z4; pb3 = z4;
        if (bRow < N) {
            const uint4* r = (const uint4*)(Bh + bOff);
            pb0 = r[0]; pb1 = r[1];
            const uint4* s = (const uint4*)(Bl + bOff);
            pb2 = s[0]; pb3 = s[1];
        }
        *(uint4*)&sAh[sOff] = pa0; *(uint4*)&sAh[sOff + 8] = pa1;
        *(uint4*)&sAl[sOff] = pa2; *(uint4*)&sAl[sOff + 8] = pa3;
        *(uint4*)&sBh[sOff] = pb0; *(uint4*)&sBh[sOff + 8] = pb1;
        *(uint4*)&sBl[sOff] = pb2; *(uint4*)&sBl[sOff + 8] = pb3;
    }
    __syncthreads();

    for (int t0 = 0; t0 < nT; t0++) {
        const bool more = (t0 + 1 < nT);
        if (more) {
            const int k1 = (t0 + 1) * 32;
            const uint4* p = (const uint4*)(Ah + aOff + k1);
            pa0 = p[0]; pa1 = p[1];
            const uint4* q = (const uint4*)(Al + aOff + k1);
            pa2 = q[0]; pa3 = q[1];
            pb0 = z4; pb1 = z4; pb2 = z4; pb3 = z4;
            if (bRow < N) {
                const uint4* r = (const uint4*)(Bh + bOff + k1);
                pb0 = r[0]; pb1 = r[1];
                const uint4* s = (const uint4*)(Bl + bOff + k1);
                pb2 = s[0]; pb3 = s[1];
            }
        }

        #pragma unroll
        for (int ks = 0; ks < 32; ks += 16) {
            u32 ah[4][4], al[4][4], bh[4][2], bl[4][2];
            #pragma unroll
            for (int t = 0; t < 4; t++) {
                u32 off = (u32)(t * 16 * 80 + ks * 2) + aLOff;
                ldsm_x4(ah[t][0], ah[t][1], ah[t][2], ah[t][3], baseAh + off);
                ldsm_x4(al[t][0], al[t][1], al[t][2], al[t][3], baseAl + off);
            }
            #pragma unroll
            for (int up = 0; up < 2; up++) {
                u32 off = (u32)(up * 16 * 80 + ks * 2) + bLOff;
                ldsm_x4(bh[2*up][0], bh[2*up][1], bh[2*up+1][0], bh[2*up+1][1],
                        baseBh + off);
                ldsm_x4(bl[2*up][0], bl[2*up][1], bl[2*up+1][0], bl[2*up+1][1],
                        baseBl + off);
            }
            #pragma unroll
            for (int t = 0; t < 4; t++)
                #pragma unroll
                for (int u = 0; u < 4; u++)
                    mma_bf16(c[t][u], ah[t], bh[u][0], bh[u][1]);
            #pragma unroll
            for (int t = 0; t < 4; t++)
                #pragma unroll
                for (int u = 0; u < 4; u++)
                    mma_bf16(c[t][u], al[t], bh[u][0], bh[u][1]);
            #pragma unroll
            for (int t = 0; t < 4; t++)
                #pragma unroll
                for (int u = 0; u < 4; u++)
                    mma_bf16(c[t][u], ah[t], bl[u][0], bl[u][1]);
        }
        __syncthreads();

        if (more) {
            *(uint4*)&sAh[sOff] = pa0; *(uint4*)&sAh[sOff + 8] = pa1;
            *(uint4*)&sAl[sOff] = pa2; *(uint4*)&sAl[sOff + 8] = pa3;
            *(uint4*)&sBh[sOff] = pb0; *(uint4*)&sBh[sOff + 8] = pb1;
            *(uint4*)&sBl[sOff] = pb2; *(uint4*)&sBl[sOff + 8] = pb3;
            __syncthreads();
        }
    }

    // ---- epilogue -----------------------------------------------------------
    float colS[8], colQ[8];
    #pragma unroll
    for (int j = 0; j < 8; j++) { colS[j] = 0.f; colQ[j] = 0.f; }

    #pragma unroll
    for (int t = 0; t < 4; t++) {
        const int r0 = m0 + wm + t * 16 + g;
        const int r1 = r0 + 8;
        #pragma unroll
        for (int u = 0; u < 4; u++) {
            const int colb = n0 + wn + u * 8 + 2 * tg;   // always even
            if (colb >= N) continue;
            const float bv0 = bp[colb];
            const float bv1 = (colb + 1 < N) ? bp[colb + 1] : 0.f;
            float x0 = c[t][u][0] + bv0, x1 = c[t][u][1] + bv1;
            float x2 = c[t][u][2] + bv0, x3 = c[t][u][3] + bv1;
            if (RELU) {
                x0 = fmaxf(x0, 0.f); x1 = fmaxf(x1, 0.f);
                x2 = fmaxf(x2, 0.f); x3 = fmaxf(x3, 0.f);
            }
            if (OUTMODE == 0) {
                const size_t i0 = (size_t)r0 * N + colb;
                const size_t i1 = (size_t)r1 * N + colb;
                if (colb + 1 < N) {
                    if ((i0 + 2) * 4 <= cBudget) *(float2*)(Cext + i0) = make_float2(x0, x1);
                    if ((i1 + 2) * 4 <= cBudget) *(float2*)(Cext + i1) = make_float2(x2, x3);
                } else {
                    if ((i0 + 1) * 4 <= cBudget) Cext[i0] = x0;
                    if ((i1 + 1) * 4 <= cBudget) Cext[i1] = x2;
                }
            } else if (OUTMODE == 2 || (OUTMODE == 3 && colb < 400)) {
                __nv_bfloat16 h0, l0, h1, l1;
                bsplit(x0, h0, l0); bsplit(x1, h1, l1);
                *(u32*)&g_mh[(size_t)r0 * KP_M + colb] =
                    (u32)__bfloat16_as_ushort(h0) | ((u32)__bfloat16_as_ushort(h1) << 16);
                *(u32*)&g_ml[(size_t)r0 * KP_M + colb] =
                    (u32)__bfloat16_as_ushort(l0) | ((u32)__bfloat16_as_ushort(l1) << 16);
                bsplit(x2, h0, l0); bsplit(x3, h1, l1);
                *(u32*)&g_mh[(size_t)r1 * KP_M + colb] =
                    (u32)__bfloat16_as_ushort(h0) | ((u32)__bfloat16_as_ushort(h1) << 16);
                *(u32*)&g_ml[(size_t)r1 * KP_M + colb] =
                    (u32)__bfloat16_as_ushort(l0) | ((u32)__bfloat16_as_ushort(l1) << 16);
            } else if (OUTMODE == 3) {
                const int cc = colb - 400;            // 0..148, even
                *(float2*)(g_ap + (size_t)r0 * 150 + cc) = make_float2(x0, x1);
                *(float2*)(g_ap + (size_t)r1 * 150 + cc) = make_float2(x2, x3);
            }
            if (STATS) {
                const int j = u * 2;
                colS[j] += x0 + x2; colQ[j] += x0 * x0 + x2 * x2;
                if (colb + 1 < N) { colS[j+1] += x1 + x3; colQ[j+1] += x1*x1 + x3*x3; }
            }
        }
    }

    if (STATS) {
        #pragma unroll
        for (int u = 0; u < 4; u++)
            #pragma unroll
            for (int p = 0; p < 2; p++) {
                int ln = wn + u * 8 + 2 * tg + p;
                atomicAdd(&sSum[ln], colS[u * 2 + p]);
                atomicAdd(&sSq [ln], colQ[u * 2 + p]);
            }
        __syncthreads();
        if (tid < 128) {
            int n = n0 + tid;
            if (n < N) {
                atomicAdd(&g_sum[statOff + n], sSum[tid]);
                atomicAdd(&g_sq [statOff + n], sSq [tid]);
            }
        }
    }
}

// ============================================================================
// Layer-1 GEMM (K=24, N=300): fp32 compute, writes h as bf16 split planes.
// ============================================================================
__global__ void __launch_bounds__(128)
fgemm1_kernel(const float* __restrict__ A, const float* __restrict__ W,
              const float* __restrict__ bias, int N, int K)
{
    const int BN = 64, BK = 16;
    __shared__ __align__(16) float As[BK][128];
    __shared__ __align__(16) float Ws[BK][BN];
    __shared__ float sSum[BN], sSq[BN];

    const int m0  = blockIdx.y * 128;
    const int n0  = blockIdx.x * BN;
    const int tid = threadIdx.x;
    const int mg  = tid >> 3;
    const int ng  = tid & 7;
    const int wk  = tid >> 3;
    const int wn  = (tid & 7) * 8;

    const float* Arow = A + (size_t)(m0 + tid) * K;

    float acc[8][8];
    #pragma unroll
    for (int i = 0; i < 8; i++)
        #pragma unroll
        for (int j = 0; j < 8; j++) acc[i][j] = 0.f;

    for (int k0 = 0; k0 < K; k0 += BK) {
        #pragma unroll
        for (int q = 0; q < 16; q++) {
            int k = k0 + q;
            As[q][tid] = (k < K) ? Arow[k] : 0.f;
        }
        {
            int k = k0 + wk, n = n0 + wn;
            float t[8];
            #pragma unroll
            for (int j = 0; j < 8; j++)
                t[j] = (k < K && n + j < N) ? W[(size_t)k * N + n + j] : 0.f;
            *(float4*)&Ws[wk][wn]     = make_float4(t[0], t[1], t[2], t[3]);
            *(float4*)&Ws[wk][wn + 4] = make_float4(t[4], t[5], t[6], t[7]);
        }
        __syncthreads();
        #pragma unroll
        for (int kk = 0; kk < BK; kk++) {
            float4 a0 = *(const float4*)&As[kk][mg * 8];
            float4 a1 = *(const float4*)&As[kk][mg * 8 + 4];
            float4 b0 = *(const float4*)&Ws[kk][ng * 4];
            float4 b1 = *(const float4*)&Ws[kk][32 + ng * 4];
            float ar[8] = {a0.x,a0.y,a0.z,a0.w,a1.x,a1.y,a1.z,a1.w};
            float br[8] = {b0.x,b0.y,b0.z,b0.w,b1.x,b1.y,b1.z,b1.w};
            #pragma unroll
            for (int i = 0; i < 8; i++)
                #pragma unroll
                for (int j = 0; j < 8; j++)
                    acc[i][j] = fmaf(ar[i], br[j], acc[i][j]);
        }
        __syncthreads();
    }

    float colSum[8], colSq[8];
    #pragma unroll
    for (int j = 0; j < 8; j++) { colSum[j] = 0.f; colSq[j] = 0.f; }

    const int cA = n0 + ng * 4;
    const int cB = n0 + 32 + ng * 4;
    float bvA[4], bvB[4];
    #pragma unroll
    for (int j = 0; j < 4; j++) {
        bvA[j] = (cA + j < N) ? bias[cA + j] : 0.f;
        bvB[j] = (cB + j < N) ? bias[cB + j] : 0.f;
    }

    #pragma unroll
    for (int i = 0; i < 8; i++) {
        const int m = m0 + mg * 8 + i;
        const size_t rb = (size_t)m * KP_H;
        float vA[4], vB[4];
        #pragma unroll
        for (int j = 0; j < 4; j++) {
            float cc = fmaxf(acc[i][j] + bvA[j], 0.f);
            vA[j] = cc;
            if (cA + j < N) { colSum[j] += cc; colSq[j] += cc * cc; }
            cc = fmaxf(acc[i][4 + j] + bvB[j], 0.f);
            vB[j] = cc;
            if (cB + j < N) { colSum[4 + j] += cc; colSq[4 + j] += cc * cc; }
        }
        if (cA < N) {
            __nv_bfloat16 h0,l0,h1,l1;
            #pragma unroll
            for (int p = 0; p < 2; p++) {
                bsplit(vA[2*p], h0, l0); bsplit(vA[2*p+1], h1, l1);
                *(u32*)&g_hh[rb + cA + 2*p] =
                    (u32)__bfloat16_as_ushort(h0) | ((u32)__bfloat16_as_ushort(h1) << 16);
                *(u32*)&g_hl[rb + cA + 2*p] =
                    (u32)__bfloat16_as_ushort(l0) | ((u32)__bfloat16_as_ushort(l1) << 16);
            }
        }
        if (cB < N) {
            __nv_bfloat16 h0,l0,h1,l1;
            #pragma unroll
            for (int p = 0; p < 2; p++) {
                bsplit(vB[2*p], h0, l0); bsplit(vB[2*p+1], h1, l1);
                *(u32*)&g_hh[rb + cB + 2*p] =
                    (u32)__bfloat16_as_ushort(h0) | ((u32)__bfloat16_as_ushort(h1) << 16);
                *(u32*)&g_hl[rb + cB + 2*p] =
                    (u32)__bfloat16_as_ushort(l0) | ((u32)__bfloat16_as_ushort(l1) << 16);
            }
        }
    }

    if (tid < BN) { sSum[tid] = 0.f; sSq[tid] = 0.f; }
    __syncthreads();
    #pragma unroll
    for (int j = 0; j < 4; j++) {
        atomicAdd(&sSum[ng * 4 + j],      colSum[j]);
        atomicAdd(&sSq [ng * 4 + j],      colSq [j]);
        atomicAdd(&sSum[32 + ng * 4 + j], colSum[4 + j]);
        atomicAdd(&sSq [32 + ng * 4 + j], colSq [4 + j]);
    }
    __syncthreads();
    if (tid < BN) {
        int n = n0 + tid;
        if (n < N) {
            atomicAdd(&g_sum[n], sSum[tid]);
            atomicAdd(&g_sq [n], sSq [tid]);
        }
    }
}

// ---------------- small scalar GEMM: a = BN(ap) @ Wa2 + ba2 (N=63,K=150) ----
__global__ void __launch_bounds__(256, 4)
sgemm_kernel(const float* __restrict__ W, const float* __restrict__ bias,
             int normOff, int N, int K)
{
    const int BN = 64, BK = 8, TM = 8, TN = 4;
    __shared__ float As[BK][128];
    __shared__ float Ws[BK][BN];

    const int m0  = blockIdx.y * 128;
    const int n0  = blockIdx.x * BN;
    const int tid = threadIdx.x;
    const int tx  = tid & 15;
    const int ty  = tid >> 4;

    float acc[TM][TN];
    #pragma unroll
    for (int i = 0; i < TM; i++)
        #pragma unroll
        for (int j = 0; j < TN; j++) acc[i][j] = 0.f;

    for (int k0 = 0; k0 < K; k0 += BK) {
        #pragma unroll
        for (int i = 0; i < 4; i++) {
            int idx = tid + i * 256;
            int mm  = idx >> 3;
            int kk  = idx & 7;
            int k   = k0 + kk;
            float v = 0.f;
            if (k < K) {
                v = g_ap[(size_t)(m0 + mm) * K + k];
                v = fmaf(v, g_scale[normOff + k], g_shift[normOff + k]);
            }
            As[kk][mm] = v;
        }
        #pragma unroll
        for (int i = 0; i < 2; i++) {
            int idx = tid + i * 256;
            int kk  = idx >> 6;
            int nn  = idx & 63;
            int k   = k0 + kk, n = n0 + nn;
            Ws[kk][nn] = (k < K && n < N) ? W[(size_t)k * N + n] : 0.f;
        }
        __syncthreads();
        #pragma unroll
        for (int kk = 0; kk < BK; kk++) {
            float ar[TM], br[TN];
            #pragma unroll
            for (int i = 0; i < TM; i++) ar[i] = As[kk][ty * TM + i];
            #pragma unroll
            for (int j = 0; j < TN; j++) br[j] = Ws[kk][tx * TN + j];
            #pragma unroll
            for (int i = 0; i < TM; i++)
                #pragma unroll
                for (int j = 0; j < TN; j++)
                    acc[i][j] = fmaf(ar[i], br[j], acc[i][j]);
        }
        __syncthreads();
    }

    #pragma unroll
    for (int j = 0; j < TN; j++) {
        int n = n0 + tx * TN + j;
        if (n < N) {
            float bv = bias[n];
            #pragma unroll
            for (int i = 0; i < TM; i++)
                g_a[(size_t)(m0 + ty * TM + i) * N + n] = acc[i][j] + bv;
        }
    }
}

// ---------------- Toeplitz epilogue (REAL parts only) -----------------------
__global__ void __launch_bounds__(256)
toeplitz_real_kernel(float* __restrict__ out,
                     size_t offB, size_t offC, size_t budgetElems)
{
    __shared__ float sre[8][32];
    const int warp = threadIdx.x >> 5;
    const int lane = threadIdx.x & 31;
    const int row  = blockIdx.x * 8 + warp;

    const float* ar = g_a + (size_t)row * 63;
    float v0 = ar[lane];
    float a0 = fminf(expf(__shfl_sync(0xffffffffu, v0, 0)), 500.f);

    float re = (lane == 0) ? a0 : (0.022f * a0 * tanhf(v0));
    sre[warp][lane] = re;
    __syncwarp();

    const size_t rbase = (size_t)row * 1024 + lane;
    #pragma unroll
    for (int i = 0; i < 32; i++) {
        int d = i - lane;
        float b = (d >= 0) ? sre[warp][d]      : 0.f;
        float c = (d >= 1) ? sre[warp][32 - d] : 0.f;
        size_t ib = offB + rbase + (size_t)i * 32;
        size_t ic = offC + rbase + (size_t)i * 32;
        if (ib < budgetElems) out[ib] = b;
        if (ic < budgetElems) out[ic] = c;
    }
}

// ---------------- launch -----------------------------------------------------
extern "C" void kernel_launch(void* const* d_in, const int* in_sizes, int n_in,
                              void* d_out, int out_size)
{
    if (n_in < 17) return;

    const float* z   = (const float*)d_in[0];
    const float* W1  = (const float*)d_in[1];
    const float* b1  = (const float*)d_in[2];
    const float* g1  = (const float*)d_in[3];
    const float* be1 = (const float*)d_in[4];
    const float* W2  = (const float*)d_in[5];
    const float* b2  = (const float*)d_in[6];
    const float* g2  = (const float*)d_in[7];
    const float* be2 = (const float*)d_in[8];
    const float* W3  = (const float*)d_in[9];
    const float* b3  = (const float*)d_in[10];
    const float* Wa1 = (const float*)d_in[11];
    const float* ba1 = (const float*)d_in[12];
    const float* ga  = (const float*)d_in[13];
    const float* bea = (const float*)d_in[14];
    const float* Wa2 = (const float*)d_in[15];
    const float* ba2 = (const float*)d_in[16];

    long long Braw = (long long)in_sizes[0] / 24;
    if (Braw > BATCH) Braw = BATCH;
    Braw -= (Braw % 128);
    if (Braw <= 0) return;
    const int B = (int)Braw;
    const long long LB = (long long)B;

    float* out = (float*)d_out;
    const float invB = 1.0f / (float)B;
    const size_t budgetBytes = (size_t)out_size * 4;
    const size_t budgetElems = (size_t)out_size;
    const int mB = B / 128;

    zero_stats_kernel<<<4, 256>>>();
    padzero_kernel<<<(B * 36 + 255) / 256, 256>>>(B);

    // 1. h = relu(z @ W1 + b1) -> bf16 split planes + stats@0
    fgemm1_kernel<<<dim3(5, mB), 128>>>(z, W1, b1, 300, 24);

    finalize_stats_kernel<<<2, 256>>>(g1, be1, 0, 300, invB);

    // fold BN1 into fused [W2 | Wa1] planes (+ bias corrections)
    fold_kernel<<<400, 128>>>(W2,  b2,  0, 400, 300, KP_H, 4, 2);
    fold_kernel<<<150, 128>>>(Wa1, ba1, 0, 150, 300, KP_H, 6, 3);

    // 3+4 FUSED: [m | ap] = relu(h @ [W2'|Wa1'] + bp), N=550
    //    cols 0..399  -> m split planes, stats@300+col
    //    cols 400..549 -> g_ap f32,      stats@700+(col-400)  (=300+col)
    bgemm_kernel<true, true, 3><<<dim3(5, mB), 256>>>(
        0, KP_H, 4, 2, nullptr, 0, 300, NF, 300);

    finalize_stats_kernel<<<2, 256>>>(g2, be2, 300, 400, invB);
    finalize_stats_kernel<<<1, 256>>>(ga, bea, 700, 150, invB);

    // fold BN2 into W3
    fold_kernel<<<1024, 128>>>(W3, b3, 300, 1024, 400, KP_M, 8, 4);

    // 6. mu = m @ W3' + bp3 -> out                             [tensor]
    bgemm_kernel<false, false, 0><<<dim3(8, mB), 256>>>(
        2, KP_M, 8, 4, out, budgetBytes, 0, 1024, 400);

    // 7. a = BN(ap) @ Wa2 + ba2 -> g_a
    sgemm_kernel<<<dim3(1, mB), 256>>>(Wa2, ba2, 700, 63, 150);

    // 8. Toeplitz real parts
    toeplitz_real_kernel<<<B / 8, 256>>>(out, (size_t)LB * 1024,
                                         (size_t)LB * 2048, budgetElems);
}

// round 16
// speedup vs baseline: 2.0997x; 1.0299x over previous
#include <cuda_runtime.h>
#include <cuda_bf16.h>
#include <math.h>

#define BATCH 32768
#define EPS   1e-5f
#define KP_H  320     // padded K for h planes (K=300)
#define KP_M  416     // padded K for m planes (K=400)
#define NF    550     // fused layer-2/4 output width (400 + 150)

typedef unsigned int  u32;
typedef unsigned short u16;
typedef unsigned long long u64;

// ---------------- scratch (device globals) -----------------------------------
__device__ __nv_bfloat16 g_hh[(size_t)BATCH * KP_H], g_hl[(size_t)BATCH * KP_H];
__device__ __nv_bfloat16 g_mh[(size_t)BATCH * KP_M], g_ml[(size_t)BATCH * KP_M];
__device__ float g_ap[(size_t)BATCH * 150];
__device__ float g_a [(size_t)BATCH * 63];

// fused W2|Wa1 planes: rows 0..399 = BN1-folded W2, rows 400..549 = folded Wa1
__device__ __nv_bfloat16 g_W2h [552  * KP_H], g_W2l [552  * KP_H];
__device__ __nv_bfloat16 g_W3h [1024 * KP_M], g_W3l [1024 * KP_M];
__device__ float g_bp2[552], g_bp3[1024];

#define STATS_TOTAL 860
__device__ float g_sum  [STATS_TOTAL];
__device__ float g_sq   [STATS_TOTAL];
__device__ float g_scale[STATS_TOTAL];
__device__ float g_shift[STATS_TOTAL];

__device__ __forceinline__ __nv_bfloat16* sel_bf(int s) {
    switch (s) {
        case 0: return g_hh;   case 1: return g_hl;
        case 2: return g_mh;   case 3: return g_ml;
        case 4: return g_W2h;  case 5: return g_W2l;
        case 8: return g_W3h;  case 9: return g_W3l;
    }
    return nullptr;
}
__device__ __forceinline__ float* sel_f(int s) {
    switch (s) {
        case 2: return g_bp2;  case 4: return g_bp3;
    }
    return nullptr;
}

__global__ void zero_stats_kernel() {
    int i = blockIdx.x * blockDim.x + threadIdx.x;
    if (i < STATS_TOTAL) { g_sum[i] = 0.f; g_sq[i] = 0.f; }
}

// zero the k-padding columns of the activation planes
__global__ void padzero_kernel(int B) {
    int idx = blockIdx.x * blockDim.x + threadIdx.x;
    const __nv_bfloat16 z = __float2bfloat16(0.f);
    if (idx < B * 20) {
        int r = idx / 20, c = idx % 20;
        g_hh[(size_t)r * KP_H + 300 + c] = z;
        g_hl[(size_t)r * KP_H + 300 + c] = z;
    } else {
        idx -= B * 20;
        if (idx < B * 16) {
            int r = idx / 16, c = idx % 16;
            g_mh[(size_t)r * KP_M + 400 + c] = z;
            g_ml[(size_t)r * KP_M + 400 + c] = z;
        }
    }
}

__global__ void finalize_stats_kernel(const float* __restrict__ g,
                                      const float* __restrict__ be,
                                      int off, int n, float invB) {
    int i = blockIdx.x * blockDim.x + threadIdx.x;
    if (i < n) {
        float mean = g_sum[off + i] * invB;
        float var  = g_sq [off + i] * invB - mean * mean;
        float s    = g[i] * rsqrtf(var + EPS);
        g_scale[off + i] = s;
        g_shift[off + i] = be[i] - mean * s;
    }
}

__device__ __forceinline__ void bsplit(float v, __nv_bfloat16& h, __nv_bfloat16& l) {
    h = __float2bfloat16(v);
    l = __float2bfloat16(v - __bfloat162float(h));
}

// ---------------- weight folds -------------------------------------------------
// fused fold for W2 (cols 0..399) and Wa1 (cols 400..549) -> g_W2h/l, bp2
__global__ void __launch_bounds__(128)
fold12_kernel(const float* __restrict__ W2, const float* __restrict__ b2,
              const float* __restrict__ Wa1, const float* __restrict__ ba1)
{
    __shared__ float red[128];
    const int n = blockIdx.x;           // 0..549
    const int tid = threadIdx.x;
    const float* W; const float* bias; int N, col;
    if (n < 400) { W = W2;  bias = b2;  N = 400; col = n; }
    else         { W = Wa1; bias = ba1; N = 150; col = n - 400; }

    float acc = 0.f;
    for (int k = tid; k < KP_H; k += 128) {
        float w = 0.f, sc = 0.f, sh = 0.f;
        if (k < 300) {
            w  = W[(size_t)k * N + col];
            sc = g_scale[k];
            sh = g_shift[k];
        }
        float wp = w * sc;
        __nv_bfloat16 h, l;
        bsplit(wp, h, l);
        g_W2h[(size_t)n * KP_H + k] = h;
        g_W2l[(size_t)n * KP_H + k] = l;
        acc += sh * w;
    }
    red[tid] = acc;
    __syncthreads();
    #pragma unroll
    for (int s = 64; s > 0; s >>= 1) {
        if (tid < s) red[tid] += red[tid + s];
        __syncthreads();
    }
    if (tid == 0) g_bp2[n] = bias[n < 400 ? n : n - 400] + red[0];
}

// generic fold (W3)
__global__ void __launch_bounds__(128)
fold_kernel(const float* __restrict__ W, const float* __restrict__ bias,
            int scOff, int N, int K, int Kp, int wSel, int bpSel)
{
    __shared__ float red[128];
    const int n = blockIdx.x;
    const int tid = threadIdx.x;
    __nv_bfloat16* Wh = sel_bf(wSel);
    __nv_bfloat16* Wl = sel_bf(wSel + 1);
    float* bp = sel_f(bpSel);

    float acc = 0.f;
    for (int k = tid; k < Kp; k += 128) {
        float w = 0.f, sc = 0.f, sh = 0.f;
        if (k < K) {
            w  = W[(size_t)k * N + n];
            sc = g_scale[scOff + k];
            sh = g_shift[scOff + k];
        }
        float wp = w * sc;
        __nv_bfloat16 h, l;
        bsplit(wp, h, l);
        Wh[(size_t)n * Kp + k] = h;
        Wl[(size_t)n * Kp + k] = l;
        acc += sh * w;
    }
    red[tid] = acc;
    __syncthreads();
    #pragma unroll
    for (int s = 64; s > 0; s >>= 1) {
        if (tid < s) red[tid] += red[tid + s];
        __syncthreads();
    }
    if (tid == 0) bp[n] = bias[n] + red[0];
}

// ---------------- mma / ldmatrix / cp.async wrappers -------------------------
__device__ __forceinline__ void mma_bf16(float c[4], const u32 a[4],
                                         u32 b0, u32 b1) {
    asm volatile("mma.sync.aligned.m16n8k16.row.col.f32.bf16.bf16.f32 "
        "{%0,%1,%2,%3}, {%4,%5,%6,%7}, {%8,%9}, {%0,%1,%2,%3};"
        : "+f"(c[0]), "+f"(c[1]), "+f"(c[2]), "+f"(c[3])
        : "r"(a[0]), "r"(a[1]), "r"(a[2]), "r"(a[3]), "r"(b0), "r"(b1));
}
__device__ __forceinline__ void ldsm_x4(u32& r0, u32& r1, u32& r2, u32& r3, u32 addr) {
    asm volatile("ldmatrix.sync.aligned.m8n8.x4.shared.b16 {%0,%1,%2,%3}, [%4];"
        : "=r"(r0), "=r"(r1), "=r"(r2), "=r"(r3) : "r"(addr));
}
__device__ __forceinline__ void cp_async16(u32 dst, const void* src) {
    asm volatile("cp.async.cg.shared.global [%0], [%1], 16;"
                 :: "r"(dst), "l"(src) : "memory");
}
#define CP_COMMIT() asm volatile("cp.async.commit_group;" ::: "memory")
#define CP_WAIT1()  asm volatile("cp.async.wait_group 1;"  ::: "memory")
#define CP_WAIT0()  asm volatile("cp.async.wait_group 0;"  ::: "memory")

// ============================================================================
// bf16-split tensor GEMM, cp.async 2-stage pipeline.
// BM=128, BN=128, BK=32, 256 thr (8 warps, 2m x 4n), warp tile 64x32.
// Dynamic smem: 2 stages x (Ah|Al|Bh|Bl) x 128x40 bf16 = 81920 B.
// OUTMODE: 0 = f32 to Cext (guarded),
//          3 = FUSED: col<400 -> split g_m planes, col>=400 -> f32 g_ap
// ============================================================================
template<bool RELU, bool STATS, int OUTMODE>
__global__ void __launch_bounds__(256)
bgemm_kernel(int aSel, int aKP, int bSel, int bpSel,
             float* __restrict__ Cext, size_t cBudget,
             int statOff, int N, int K)
{
    extern __shared__ __align__(16) char dsm[];   // 2 x 40960 B
    __shared__ float sSum[128], sSq[128];

    const __nv_bfloat16* Ah = sel_bf(aSel);
    const __nv_bfloat16* Al = sel_bf(aSel + 1);
    const __nv_bfloat16* Bh = sel_bf(bSel);
    const __nv_bfloat16* Bl = sel_bf(bSel + 1);
    const float* bp = sel_f(bpSel);

    const int m0 = blockIdx.y * 128, n0 = blockIdx.x * 128;
    const int tid = threadIdx.x, wid = tid >> 5, lane = tid & 31;
    const int g = lane >> 2, tg = lane & 3;
    const int wm = (wid >> 2) * 64, wn = (wid & 3) * 32;

    if (tid < 128) { sSum[tid] = 0.f; sSq[tid] = 0.f; }

    const u32 dsmS = (u32)__cvta_generic_to_shared(dsm);
    const u32 aLOff = (u32)((wm + (lane & 15)) * 80 + (lane >> 4) * 16);
    const u32 bLOff = (u32)((wn + ((lane >> 4) & 1) * 8 + (lane & 7)) * 80
                            + ((lane >> 3) & 1) * 16);

    const int nT = (K + 31) / 32;

    // ---- cp.async staging of one 32-k tile into a stage buffer -------------
    auto issue = [&](int t, int buf) {
        const int k0 = t * 32;
        const u32 sb = dsmS + buf * 40960;
        #pragma unroll
        for (int i = 0; i < 2; i++) {
            int gid = tid + i * 256;          // 0..511
            int row = gid >> 2, seg = gid & 3;
            u32 doff = (u32)(row * 80 + seg * 16);
            size_t aoff = (size_t)(m0 + row) * aKP + k0 + seg * 8;
            cp_async16(sb + doff,         Ah + aoff);
            cp_async16(sb + 10240 + doff, Al + aoff);
            int br = n0 + row;
            if (br > N - 1) br = N - 1;       // clamp: garbage only feeds cols>=N
            size_t boff = (size_t)br * aKP + k0 + seg * 8;
            cp_async16(sb + 20480 + doff, Bh + boff);
            cp_async16(sb + 30720 + doff, Bl + boff);
        }
        CP_COMMIT();
    };

    float c[4][4][4];
    #pragma unroll
    for (int t = 0; t < 4; t++)
        #pragma unroll
        for (int u = 0; u < 4; u++)
            #pragma unroll
            for (int v = 0; v < 4; v++) c[t][u][v] = 0.f;

    issue(0, 0);
    if (nT > 1) issue(1, 1);

    for (int t0 = 0; t0 < nT; t0++) {
        if (t0 + 1 < nT) { CP_WAIT1(); } else { CP_WAIT0(); }
        __syncthreads();

        const u32 sb = dsmS + (t0 & 1) * 40960;
        #pragma unroll
        for (int ks = 0; ks < 32; ks += 16) {
            u32 ah[4][4], al[4][4], bh[4][2], bl[4][2];
            #pragma unroll
            for (int t = 0; t < 4; t++) {
                u32 off = (u32)(t * 16 * 80 + ks * 2) + aLOff;
                ldsm_x4(ah[t][0], ah[t][1], ah[t][2], ah[t][3], sb + off);
                ldsm_x4(al[t][0], al[t][1], al[t][2], al[t][3], sb + 10240 + off);
            }
            #pragma unroll
            for (int up = 0; up < 2; up++) {
                u32 off = (u32)(up * 16 * 80 + ks * 2) + bLOff;
                ldsm_x4(bh[2*up][0], bh[2*up][1], bh[2*up+1][0], bh[2*up+1][1],
                        sb + 20480 + off);
                ldsm_x4(bl[2*up][0], bl[2*up][1], bl[2*up+1][0], bl[2*up+1][1],
                        sb + 30720 + off);
            }
            #pragma unroll
            for (int t = 0; t < 4; t++)
                #pragma unroll
                for (int u = 0; u < 4; u++)
                    mma_bf16(c[t][u], ah[t], bh[u][0], bh[u][1]);
            #pragma unroll
            for (int t = 0; t < 4; t++)
                #pragma unroll
                for (int u = 0; u < 4; u++)
                    mma_bf16(c[t][u], al[t], bh[u][0], bh[u][1]);
            #pragma unroll
            for (int t = 0; t < 4; t++)
                #pragma unroll
                for (int u = 0; u < 4; u++)
                    mma_bf16(c[t][u], ah[t], bl[u][0], bl[u][1]);
        }
        __syncthreads();
        if (t0 + 2 < nT) issue(t0 + 2, t0 & 1);
    }

    // ---- epilogue -----------------------------------------------------------
    float colS[8], colQ[8];
    #pragma unroll
    for (int j = 0; j < 8; j++) { colS[j] = 0.f; colQ[j] = 0.f; }

    #pragma unroll
    for (int t = 0; t < 4; t++) {
        const int r0 = m0 + wm + t * 16 + g;
        const int r1 = r0 + 8;
        #pragma unroll
        for (int u = 0; u < 4; u++) {
            const int colb = n0 + wn + u * 8 + 2 * tg;   // always even
            if (colb >= N) continue;
            const float bv0 = bp[colb];
            const float bv1 = (colb + 1 < N) ? bp[colb + 1] : 0.f;
            float x0 = c[t][u][0] + bv0, x1 = c[t][u][1] + bv1;
            float x2 = c[t][u][2] + bv0, x3 = c[t][u][3] + bv1;
            if (RELU) {
                x0 = fmaxf(x0, 0.f); x1 = fmaxf(x1, 0.f);
                x2 = fmaxf(x2, 0.f); x3 = fmaxf(x3, 0.f);
            }
            if (OUTMODE == 0) {
                const size_t i0 = (size_t)r0 * N + colb;
                const size_t i1 = (size_t)r1 * N + colb;
                if (colb + 1 < N) {
                    if ((i0 + 2) * 4 <= cBudget) *(float2*)(Cext + i0) = make_float2(x0, x1);
                    if ((i1 + 2) * 4 <= cBudget) *(float2*)(Cext + i1) = make_float2(x2, x3);
                } else {
                    if ((i0 + 1) * 4 <= cBudget) Cext[i0] = x0;
                    if ((i1 + 1) * 4 <= cBudget) Cext[i1] = x2;
                }
            } else if (OUTMODE == 3 && colb < 400) {
                __nv_bfloat16 h0, l0, h1, l1;
                bsplit(x0, h0, l0); bsplit(x1, h1, l1);
                *(u32*)&g_mh[(size_t)r0 * KP_M + colb] =
                    (u32)__bfloat16_as_ushort(h0) | ((u32)__bfloat16_as_ushort(h1) << 16);
                *(u32*)&g_ml[(size_t)r0 * KP_M + colb] =
                    (u32)__bfloat16_as_ushort(l0) | ((u32)__bfloat16_as_ushort(l1) << 16);
                bsplit(x2, h0, l0); bsplit(x3, h1, l1);
                *(u32*)&g_mh[(size_t)r1 * KP_M + colb] =
                    (u32)__bfloat16_as_ushort(h0) | ((u32)__bfloat16_as_ushort(h1) << 16);
                *(u32*)&g_ml[(size_t)r1 * KP_M + colb] =
                    (u32)__bfloat16_as_ushort(l0) | ((u32)__bfloat16_as_ushort(l1) << 16);
            } else if (OUTMODE == 3) {
                const int cc = colb - 400;            // 0..148, even
                *(float2*)(g_ap + (size_t)r0 * 150 + cc) = make_float2(x0, x1);
                *(float2*)(g_ap + (size_t)r1 * 150 + cc) = make_float2(x2, x3);
            }
            if (STATS) {
                const int j = u * 2;
                colS[j] += x0 + x2; colQ[j] += x0 * x0 + x2 * x2;
                if (colb + 1 < N) { colS[j+1] += x1 + x3; colQ[j+1] += x1*x1 + x3*x3; }
            }
        }
    }

    if (STATS) {
        #pragma unroll
        for (int u = 0; u < 4; u++)
            #pragma unroll
            for (int p = 0; p < 2; p++) {
                int ln = wn + u * 8 + 2 * tg + p;
                atomicAdd(&sSum[ln], colS[u * 2 + p]);
                atomicAdd(&sSq [ln], colQ[u * 2 + p]);
            }
        __syncthreads();
        if (tid < 128) {
            int n = n0 + tid;
            if (n < N) {
                atomicAdd(&g_sum[statOff + n], sSum[tid]);
                atomicAdd(&g_sq [statOff + n], sSq [tid]);
            }
        }
    }
}

// ============================================================================
// Layer-1 GEMM (K=24, N=300): fp32 compute, writes h as bf16 split planes.
// ============================================================================
__global__ void __launch_bounds__(128)
fgemm1_kernel(const float* __restrict__ A, const float* __restrict__ W,
              const float* __restrict__ bias, int N, int K)
{
    const int BN = 64, BK = 16;
    __shared__ __align__(16) float As[BK][128];
    __shared__ __align__(16) float Ws[BK][BN];
    __shared__ float sSum[BN], sSq[BN];

    const int m0  = blockIdx.y * 128;
    const int n0  = blockIdx.x * BN;
    const int tid = threadIdx.x;
    const int mg  = tid >> 3;
    const int ng  = tid & 7;
    const int wk  = tid >> 3;
    const int wn  = (tid & 7) * 8;

    const float* Arow = A + (size_t)(m0 + tid) * K;

    float acc[8][8];
    #pragma unroll
    for (int i = 0; i < 8; i++)
        #pragma unroll
        for (int j = 0; j < 8; j++) acc[i][j] = 0.f;

    for (int k0 = 0; k0 < K; k0 += BK) {
        #pragma unroll
        for (int q = 0; q < 16; q++) {
            int k = k0 + q;
            As[q][tid] = (k < K) ? Arow[k] : 0.f;
        }
        {
            int k = k0 + wk, n = n0 + wn;
            float t[8];
            #pragma unroll
            for (int j = 0; j < 8; j++)
                t[j] = (k < K && n + j < N) ? W[(size_t)k * N + n + j] : 0.f;
            *(float4*)&Ws[wk][wn]     = make_float4(t[0], t[1], t[2], t[3]);
            *(float4*)&Ws[wk][wn + 4] = make_float4(t[4], t[5], t[6], t[7]);
        }
        __syncthreads();
        #pragma unroll
        for (int kk = 0; kk < BK; kk++) {
            float4 a0 = *(const float4*)&As[kk][mg * 8];
            float4 a1 = *(const float4*)&As[kk][mg * 8 + 4];
            float4 b0 = *(const float4*)&Ws[kk][ng * 4];
            float4 b1 = *(const float4*)&Ws[kk][32 + ng * 4];
            float ar[8] = {a0.x,a0.y,a0.z,a0.w,a1.x,a1.y,a1.z,a1.w};
            float br[8] = {b0.x,b0.y,b0.z,b0.w,b1.x,b1.y,b1.z,b1.w};
            #pragma unroll
            for (int i = 0; i < 8; i++)
                #pragma unroll
                for (int j = 0; j < 8; j++)
                    acc[i][j] = fmaf(ar[i], br[j], acc[i][j]);
        }
        __syncthreads();
    }

    float colSum[8], colSq[8];
    #pragma unroll
    for (int j = 0; j < 8; j++) { colSum[j] = 0.f; colSq[j] = 0.f; }

    const int cA = n0 + ng * 4;
    const int cB = n0 + 32 + ng * 4;
    float bvA[4], bvB[4];
    #pragma unroll
    for (int j = 0; j < 4; j++) {
        bvA[j] = (cA + j < N) ? bias[cA + j] : 0.f;
        bvB[j] = (cB + j < N) ? bias[cB + j] : 0.f;
    }

    #pragma unroll
    for (int i = 0; i < 8; i++) {
        const int m = m0 + mg * 8 + i;
        const size_t rb = (size_t)m * KP_H;
        float vA[4], vB[4];
        #pragma unroll
        for (int j = 0; j < 4; j++) {
            float cc = fmaxf(acc[i][j] + bvA[j], 0.f);
            vA[j] = cc;
            if (cA + j < N) { colSum[j] += cc; colSq[j] += cc * cc; }
            cc = fmaxf(acc[i][4 + j] + bvB[j], 0.f);
            vB[j] = cc;
            if (cB + j < N) { colSum[4 + j] += cc; colSq[4 + j] += cc * cc; }
        }
        if (cA < N) {
            __nv_bfloat16 h0,l0,h1,l1;
            #pragma unroll
            for (int p = 0; p < 2; p++) {
                bsplit(vA[2*p], h0, l0); bsplit(vA[2*p+1], h1, l1);
                *(u32*)&g_hh[rb + cA + 2*p] =
                    (u32)__bfloat16_as_ushort(h0) | ((u32)__bfloat16_as_ushort(h1) << 16);
                *(u32*)&g_hl[rb + cA + 2*p] =
                    (u32)__bfloat16_as_ushort(l0) | ((u32)__bfloat16_as_ushort(l1) << 16);
            }
        }
        if (cB < N) {
            __nv_bfloat16 h0,l0,h1,l1;
            #pragma unroll
            for (int p = 0; p < 2; p++) {
                bsplit(vB[2*p], h0, l0); bsplit(vB[2*p+1], h1, l1);
                *(u32*)&g_hh[rb + cB + 2*p] =
                    (u32)__bfloat16_as_ushort(h0) | ((u32)__bfloat16_as_ushort(h1) << 16);
                *(u32*)&g_hl[rb + cB + 2*p] =
                    (u32)__bfloat16_as_ushort(l0) | ((u32)__bfloat16_as_ushort(l1) << 16);
            }
        }
    }

    if (tid < BN) { sSum[tid] = 0.f; sSq[tid] = 0.f; }
    __syncthreads();
    #pragma unroll
    for (int j = 0; j < 4; j++) {
        atomicAdd(&sSum[ng * 4 + j],      colSum[j]);
        atomicAdd(&sSq [ng * 4 + j],      colSq [j]);
        atomicAdd(&sSum[32 + ng * 4 + j], colSum[4 + j]);
        atomicAdd(&sSq [32 + ng * 4 + j], colSq [4 + j]);
    }
    __syncthreads();
    if (tid < BN) {
        int n = n0 + tid;
        if (n < N) {
            atomicAdd(&g_sum[n], sSum[tid]);
            atomicAdd(&g_sq [n], sSq [tid]);
        }
    }
}

// ---------------- small scalar GEMM: a = BN(ap) @ Wa2 + ba2 (N=63,K=150) ----
__global__ void __launch_bounds__(256, 4)
sgemm_kernel(const float* __restrict__ W, const float* __restrict__ bias,
             int normOff, int N, int K)
{
    const int BN = 64, BK = 8, TM = 8, TN = 4;
    __shared__ float As[BK][128];
    __shared__ float Ws[BK][BN];

    const int m0  = blockIdx.y * 128;
    const int n0  = blockIdx.x * BN;
    const int tid = threadIdx.x;
    const int tx  = tid & 15;
    const int ty  = tid >> 4;

    float acc[TM][TN];
    #pragma unroll
    for (int i = 0; i < TM; i++)
        #pragma unroll
        for (int j = 0; j < TN; j++) acc[i][j] = 0.f;

    for (int k0 = 0; k0 < K; k0 += BK) {
        #pragma unroll
        for (int i = 0; i < 4; i++) {
            int idx = tid + i * 256;
            int mm  = idx >> 3;
            int kk  = idx & 7;
            int k   = k0 + kk;
            float v = 0.f;
            if (k < K) {
                v = g_ap[(size_t)(m0 + mm) * K + k];
                v = fmaf(v, g_scale[normOff + k], g_shift[normOff + k]);
            }
            As[kk][mm] = v;
        }
        #pragma unroll
        for (int i = 0; i < 2; i++) {
            int idx = tid + i * 256;
            int kk  = idx >> 6;
            int nn  = idx & 63;
            int k   = k0 + kk, n = n0 + nn;
            Ws[kk][nn] = (k < K && n < N) ? W[(size_t)k * N + n] : 0.f;
        }
        __syncthreads();
        #pragma unroll
        for (int kk = 0; kk < BK; kk++) {
            float ar[TM], br[TN];
            #pragma unroll
            for (int i = 0; i < TM; i++) ar[i] = As[kk][ty * TM + i];
            #pragma unroll
            for (int j = 0; j < TN; j++) br[j] = Ws[kk][tx * TN + j];
            #pragma unroll
            for (int i = 0; i < TM; i++)
                #pragma unroll
                for (int j = 0; j < TN; j++)
                    acc[i][j] = fmaf(ar[i], br[j], acc[i][j]);
        }
        __syncthreads();
    }

    #pragma unroll
    for (int j = 0; j < TN; j++) {
        int n = n0 + tx * TN + j;
        if (n < N) {
            float bv = bias[n];
            #pragma unroll
            for (int i = 0; i < TM; i++)
                g_a[(size_t)(m0 + ty * TM + i) * N + n] = acc[i][j] + bv;
        }
    }
}

// ---------------- Toeplitz epilogue (REAL parts only) -----------------------
__global__ void __launch_bounds__(256)
toeplitz_real_kernel(float* __restrict__ out,
                     size_t offB, size_t offC, size_t budgetElems)
{
    __shared__ float sre[8][32];
    const int warp = threadIdx.x >> 5;
    const int lane = threadIdx.x & 31;
    const int row  = blockIdx.x * 8 + warp;

    const float* ar = g_a + (size_t)row * 63;
    float v0 = ar[lane];
    float a0 = fminf(expf(__shfl_sync(0xffffffffu, v0, 0)), 500.f);

    float re = (lane == 0) ? a0 : (0.022f * a0 * tanhf(v0));
    sre[warp][lane] = re;
    __syncwarp();

    const size_t rbase = (size_t)row * 1024 + lane;
    #pragma unroll
    for (int i = 0; i < 32; i++) {
        int d = i - lane;
        float b = (d >= 0) ? sre[warp][d]      : 0.f;
        float c = (d >= 1) ? sre[warp][32 - d] : 0.f;
        size_t ib = offB + rbase + (size_t)i * 32;
        size_t ic = offC + rbase + (size_t)i * 32;
        if (ib < budgetElems) out[ib] = b;
        if (ic < budgetElems) out[ic] = c;
    }
}

// ---------------- launch -----------------------------------------------------
extern "C" void kernel_launch(void* const* d_in, const int* in_sizes, int n_in,
                              void* d_out, int out_size)
{
    if (n_in < 17) return;

    const float* z   = (const float*)d_in[0];
    const float* W1  = (const float*)d_in[1];
    const float* b1  = (const float*)d_in[2];
    const float* g1  = (const float*)d_in[3];
    const float* be1 = (const float*)d_in[4];
    const float* W2  = (const float*)d_in[5];
    const float* b2  = (const float*)d_in[6];
    const float* g2  = (const float*)d_in[7];
    const float* be2 = (const float*)d_in[8];
    const float* W3  = (const float*)d_in[9];
    const float* b3  = (const float*)d_in[10];
    const float* Wa1 = (const float*)d_in[11];
    const float* ba1 = (const float*)d_in[12];
    const float* ga  = (const float*)d_in[13];
    const float* bea = (const float*)d_in[14];
    const float* Wa2 = (const float*)d_in[15];
    const float* ba2 = (const float*)d_in[16];

    long long Braw = (long long)in_sizes[0] / 24;
    if (Braw > BATCH) Braw = BATCH;
    Braw -= (Braw % 128);
    if (Braw <= 0) return;
    const int B = (int)Braw;
    const long long LB = (long long)B;

    float* out = (float*)d_out;
    const float invB = 1.0f / (float)B;
    const size_t budgetBytes = (size_t)out_size * 4;
    const size_t budgetElems = (size_t)out_size;
    const int mB = B / 128;
    const int DSM = 81920;

    static int attrDone = 0;
    if (!attrDone) {
        cudaFuncSetAttribute(bgemm_kernel<true, true, 3>,
                             cudaFuncAttributeMaxDynamicSharedMemorySize, DSM);
        cudaFuncSetAttribute(bgemm_kernel<false, false, 0>,
                             cudaFuncAttributeMaxDynamicSharedMemorySize, DSM);
        attrDone = 1;
    }

    zero_stats_kernel<<<4, 256>>>();
    padzero_kernel<<<(B * 36 + 255) / 256, 256>>>(B);

    // 1. h = relu(z @ W1 + b1) -> bf16 split planes + stats@0
    fgemm1_kernel<<<dim3(5, mB), 128>>>(z, W1, b1, 300, 24);

    finalize_stats_kernel<<<2, 256>>>(g1, be1, 0, 300, invB);

    // fold BN1 into fused [W2 | Wa1] planes (single launch)
    fold12_kernel<<<550, 128>>>(W2, b2, Wa1, ba1);

    // 3+4 FUSED: [m | ap] = relu(h @ [W2'|Wa1'] + bp), N=550
    bgemm_kernel<true, true, 3><<<dim3(5, mB), 256, DSM>>>(
        0, KP_H, 4, 2, nullptr, 0, 300, NF, 300);

    finalize_stats_kernel<<<2, 256>>>(g2, be2, 300, 400, invB);
    finalize_stats_kernel<<<1, 256>>>(ga, bea, 700, 150, invB);

    // fold BN2 into W3
    fold_kernel<<<1024, 128>>>(W3, b3, 300, 1024, 400, KP_M, 8, 4);

    // 6. mu = m @ W3' + bp3 -> out
    bgemm_kernel<false, false, 0><<<dim3(8, mB), 256, DSM>>>(
        2, KP_M, 8, 4, out, budgetBytes, 0, 1024, 400);

    // 7. a = BN(ap) @ Wa2 + ba2 -> g_a
    sgemm_kernel<<<dim3(1, mB), 256>>>(Wa2, ba2, 700, 63, 150);

    // 8. Toeplitz real parts
    toeplitz_real_kernel<<<B / 8, 256>>>(out, (size_t)LB * 1024,
                                         (size_t)LB * 2048, budgetElems);
}